// round 3
// baseline (speedup 1.0000x reference)
#include <cuda_runtime.h>
#include <math.h>

// ---------------- problem constants ----------------
#define BB     8
#define HH     128
#define WW     384
#define CC     192
#define NHEAD  6
#define WSZ    8
#define SSZ    4
#define HDIM   32
#define NWIN   768                 // windows per batch image (16*48)
#define NTOK   64                  // tokens per window
#define HWSZ   (HH*WW)             // 49152
#define MTOK   (BB*HWSZ)           // 393216 total tokens
#define C3     (3*CC)              // 576
#define MLPH   (4*CC)              // 768
#define SCALE  0.1767766952966369f // 32^-0.5
#define MCHUNK (MTOK/4)            // 98304 rows per MLP chunk

// ---------------- scratch (device globals; ALIASED by live range) ---------
// Keep total small: nvcc makes same-size host shadow symbols; >2GB of .bss
// breaks host linking (GOTPCREL relaxation). Total here: 1.2 GB.
//
// g_bufA (MTOK*CC floats, 302MB):
//   phase 1: LN1 output in window layout ("win")
//   phase 3: attention output ("att")           [win dead after QKV GEMM]
//   phase 6: fc1+gelu chunk (MCHUNK*MLPH = MTOK*CC exactly)  [att dead]
// g_bufB (MTOK*C3 floats, 906MB):
//   phase 2: qkv
//   phase 4+: x1 at offset 0, h2 at offset MTOK*CC   [qkv dead after attn]
__device__ float g_bufA[(size_t)MTOK * CC];
__device__ float g_bufB[(size_t)MTOK * C3];

// window-layout row m  ->  original token index (same map for gather & scatter:
// forward uses roll(-4) gather, reverse uses roll(+4) scatter; both reduce to
// token (b, (sh+4)%128, (sw+4)%384)).
__device__ __forceinline__ int win_to_tok(int m) {
    int b  = m / HWSZ;
    int r  = m - b * HWSZ;
    int w  = r >> 6;            // window id within batch
    int nt = r & 63;            // token within window
    int wrow = w / 48;
    int wcol = w - wrow * 48;
    int sh = (wrow << 3) + (nt >> 3);
    int sw = (wcol << 3) + (nt & 7);
    int fh = (sh + SSZ) & (HH - 1);
    int fw = sw + SSZ; if (fw >= WW) fw -= WW;
    return b * HWSZ + fh * WW + fw;
}

// ---------------- LayerNorm (one warp per token, C=192 = 6 per lane) ------
template<bool GATHER>
__global__ void ln_kernel(const float* __restrict__ x,
                          const float* __restrict__ gamma,
                          const float* __restrict__ beta,
                          float* __restrict__ out) {
    int warp = blockIdx.x * (blockDim.x >> 5) + (threadIdx.x >> 5);
    if (warp >= MTOK) return;
    int lane = threadIdx.x & 31;
    int src = GATHER ? win_to_tok(warp) : warp;
    const float* xr = x + (size_t)src * CC;
    float v[6], s = 0.f, ss = 0.f;
#pragma unroll
    for (int i = 0; i < 6; i++) {
        float t = xr[lane + i * 32];
        v[i] = t; s += t; ss += t * t;
    }
#pragma unroll
    for (int o = 16; o; o >>= 1) {
        s  += __shfl_xor_sync(0xffffffffu, s,  o);
        ss += __shfl_xor_sync(0xffffffffu, ss, o);
    }
    float mean = s * (1.f / CC);
    float var  = ss * (1.f / CC) - mean * mean;
    float rstd = rsqrtf(var + 1e-5f);
    float* orow = out + (size_t)warp * CC;
#pragma unroll
    for (int i = 0; i < 6; i++) {
        int c = lane + i * 32;
        orow[c] = (v[i] - mean) * rstd * gamma[c] + beta[c];
    }
}

// ---------------- SGEMM: out[m,n] = sum_k A[m,k]*W[n,k] (+epilogue) -------
// A row-major [M,K], W row-major [N,K]. BM=128 BN=64 BK=16, 256 threads,
// 8x4 per-thread micro-tile. Exact tiling (no bounds checks): for all GEMMs
// M%128==0, N%64==0, K%16==0.
#define EPI_BIAS 0   // out = acc + bias
#define EPI_PROJ 1   // scatter via win_to_tok; out[dst] = res[dst] + acc + bias
#define EPI_GELU 2   // out = gelu(acc + bias)   (exact erf)
#define EPI_RES  3   // out = res + acc + bias

template<int EPI>
__global__ __launch_bounds__(256)
void gemm_kernel(const float* __restrict__ A, const float* __restrict__ W,
                 const float* __restrict__ bias, const float* __restrict__ res,
                 float* __restrict__ out, int M, int N, int K) {
    constexpr int BM = 128, BN = 64, BK = 16, TM = 8, TN = 4;
    __shared__ float As[BK][BM];
    __shared__ float Bs[BK][BN];

    int tid = threadIdx.x;
    int m0 = blockIdx.y * BM;
    int n0 = blockIdx.x * BN;

    int aRow = tid >> 2;            // 0..63
    int aCol = (tid & 3) << 2;      // 0,4,8,12
    int bRow = tid >> 2;            // n 0..63
    int bCol = (tid & 3) << 2;      // k

    int tr = (tid >> 4) * TM;       // micro-tile row base (0..120)
    int tc = (tid & 15) * TN;       // micro-tile col base (0..60)

    float acc[TM][TN] = {};

    for (int k0 = 0; k0 < K; k0 += BK) {
#pragma unroll
        for (int r = 0; r < BM; r += 64) {
            float4 t = *(const float4*)(A + (size_t)(m0 + aRow + r) * K + k0 + aCol);
            As[aCol + 0][aRow + r] = t.x;
            As[aCol + 1][aRow + r] = t.y;
            As[aCol + 2][aRow + r] = t.z;
            As[aCol + 3][aRow + r] = t.w;
        }
        {
            float4 t = *(const float4*)(W + (size_t)(n0 + bRow) * K + k0 + bCol);
            Bs[bCol + 0][bRow] = t.x;
            Bs[bCol + 1][bRow] = t.y;
            Bs[bCol + 2][bRow] = t.z;
            Bs[bCol + 3][bRow] = t.w;
        }
        __syncthreads();
#pragma unroll
        for (int kk = 0; kk < BK; kk++) {
            float4 rm0 = *(const float4*)&As[kk][tr];
            float4 rm1 = *(const float4*)&As[kk][tr + 4];
            float4 rn  = *(const float4*)&Bs[kk][tc];
            float rm[TM] = {rm0.x, rm0.y, rm0.z, rm0.w, rm1.x, rm1.y, rm1.z, rm1.w};
            float rn_[TN] = {rn.x, rn.y, rn.z, rn.w};
#pragma unroll
            for (int i = 0; i < TM; i++)
#pragma unroll
                for (int j = 0; j < TN; j++)
                    acc[i][j] = fmaf(rm[i], rn_[j], acc[i][j]);
        }
        __syncthreads();
    }

#pragma unroll
    for (int i = 0; i < TM; i++) {
        int m = m0 + tr + i;
        int dst = (EPI == EPI_PROJ) ? win_to_tok(m) : m;
#pragma unroll
        for (int j = 0; j < TN; j++) {
            int n = n0 + tc + j;
            float v = acc[i][j] + bias[n];
            size_t oi = (size_t)dst * N + n;
            if (EPI == EPI_BIAS) {
                out[oi] = v;
            } else if (EPI == EPI_PROJ) {
                out[oi] = res[oi] + v;
            } else if (EPI == EPI_GELU) {
                out[oi] = 0.5f * v * (1.f + erff(v * 0.70710678118654752f));
            } else { // EPI_RES
                out[oi] = res[oi] + v;
            }
        }
    }
}

// ---------------- windowed attention: one block per (window, head) --------
// qkv row layout per token: [q(6*32) | k(6*32) | v(6*32)], head h at h*32.
__global__ __launch_bounds__(128)
void attn_kernel(const float* __restrict__ qkv,
                 const float* __restrict__ rpb,      // [225, 6]
                 const int*   __restrict__ rel_idx,  // [64*64]
                 const float* __restrict__ mask,     // [768, 64, 64]
                 float* __restrict__ out) {          // [M, 192] window layout
    __shared__ float q[NTOK][HDIM];
    __shared__ float k[NTOK][HDIM + 1];  // pad: avoid 32-way conflict in QK^T
    __shared__ float v[NTOK][HDIM];
    __shared__ float S[NTOK][NTOK + 1];

    int wg   = blockIdx.x;   // 0..6143 (global window)
    int head = blockIdx.y;   // 0..5
    int tid  = threadIdx.x;  // 128 threads

    const float* base = qkv + (size_t)wg * NTOK * C3 + head * HDIM;
    for (int idx = tid; idx < NTOK * HDIM; idx += 128) {
        int n = idx >> 5, d = idx & 31;
        const float* row = base + (size_t)n * C3 + d;
        q[n][d] = row[0];
        k[n][d] = row[CC];
        v[n][d] = row[2 * CC];
    }
    __syncthreads();

    const float* mrow = mask + (size_t)(wg % NWIN) * NTOK * NTOK;
    for (int e = tid; e < NTOK * NTOK; e += 128) {
        int n = e >> 6, mm = e & 63;
        float acc = 0.f;
#pragma unroll
        for (int d = 0; d < HDIM; d++) acc = fmaf(q[n][d], k[mm][d], acc);
        float bias = rpb[rel_idx[e] * NHEAD + head];
        S[n][mm] = acc * SCALE + bias + mrow[e];
    }
    __syncthreads();

    if (tid < NTOK) {
        float mx = -1e30f;
#pragma unroll 8
        for (int mm = 0; mm < NTOK; mm++) mx = fmaxf(mx, S[tid][mm]);
        float sum = 0.f;
#pragma unroll 8
        for (int mm = 0; mm < NTOK; mm++) {
            float e = expf(S[tid][mm] - mx);
            S[tid][mm] = e; sum += e;
        }
        float inv = 1.f / sum;
#pragma unroll 8
        for (int mm = 0; mm < NTOK; mm++) S[tid][mm] *= inv;
    }
    __syncthreads();

    float* orow = out + (size_t)wg * NTOK * CC + head * HDIM;
    for (int e = tid; e < NTOK * HDIM; e += 128) {
        int n = e >> 5, d = e & 31;
        float acc = 0.f;
#pragma unroll
        for (int mm = 0; mm < NTOK; mm++) acc = fmaf(S[n][mm], v[mm][d], acc);
        orow[(size_t)n * CC + d] = acc;
    }
}

// ---------------- launch ---------------------------------------------------
extern "C" void kernel_launch(void* const* d_in, const int* in_sizes, int n_in,
                              void* d_out, int out_size) {
    const float* x        = (const float*)d_in[0];
    const float* qkv_w    = (const float*)d_in[1];
    const float* qkv_b    = (const float*)d_in[2];
    const float* rpb      = (const float*)d_in[3];
    const float* proj_w   = (const float*)d_in[4];
    const float* proj_b   = (const float*)d_in[5];
    const float* g1       = (const float*)d_in[6];
    const float* b1       = (const float*)d_in[7];
    const float* g2       = (const float*)d_in[8];
    const float* b2       = (const float*)d_in[9];
    const float* fc1_w    = (const float*)d_in[10];
    const float* fc1_b    = (const float*)d_in[11];
    const float* fc2_w    = (const float*)d_in[12];
    const float* fc2_b    = (const float*)d_in[13];
    const int*   rel_idx  = (const int*)  d_in[14];
    const float* amask    = (const float*)d_in[15];
    float* out = (float*)d_out;

    float *bufA, *bufB;
    cudaGetSymbolAddress((void**)&bufA, g_bufA);
    cudaGetSymbolAddress((void**)&bufB, g_bufB);

    float* win  = bufA;                        // phase 1-2
    float* qkvb = bufB;                        // phase 2-3
    float* att  = bufA;                        // phase 3-4 (win dead)
    float* x1   = bufB;                        // phase 4+  (qkv dead)
    float* h2   = bufB + (size_t)MTOK * CC;    // phase 5+
    float* mlpc = bufA;                        // phase 6-7 chunks (att dead)

    const int LN_BLOCKS = MTOK / 8;   // 8 warps (256 threads) per block

    // 1) LN1 + shift + window partition (gather)
    ln_kernel<true><<<LN_BLOCKS, 256>>>(x, g1, b1, win);

    // 2) QKV GEMM  [M,192] x [576,192]^T -> [M,576]
    gemm_kernel<EPI_BIAS><<<dim3(C3 / 64, MTOK / 128), 256>>>(
        win, qkv_w, qkv_b, nullptr, qkvb, MTOK, C3, CC);

    // 3) attention per (window, head)
    attn_kernel<<<dim3(BB * NWIN, NHEAD), 128>>>(qkvb, rpb, rel_idx, amask, att);

    // 4) proj GEMM + window-reverse/unshift scatter + residual -> x1
    gemm_kernel<EPI_PROJ><<<dim3(CC / 64, MTOK / 128), 256>>>(
        att, proj_w, proj_b, x, x1, MTOK, CC, CC);

    // 5) LN2
    ln_kernel<false><<<LN_BLOCKS, 256>>>(x1, g2, b2, h2);

    // 6/7) MLP in 4 row-chunks to keep scratch at MTOK*CC floats
    for (int c = 0; c < 4; c++) {
        size_t roff = (size_t)c * MCHUNK;
        // fc1 + exact GELU  [Mc,192] x [768,192]^T -> mlp chunk [Mc,768]
        gemm_kernel<EPI_GELU><<<dim3(MLPH / 64, MCHUNK / 128), 256>>>(
            h2 + roff * CC, fc1_w, fc1_b, nullptr, mlpc, MCHUNK, MLPH, CC);
        // fc2 + residual -> d_out  [Mc,768] x [192,768]^T -> [Mc,192]
        gemm_kernel<EPI_RES><<<dim3(CC / 64, MCHUNK / 128), 256>>>(
            mlpc, fc2_w, fc2_b, x1 + roff * CC, out + roff * CC,
            MCHUNK, CC, MLPH);
    }

    (void)in_sizes; (void)n_in; (void)out_size;
}

// round 4
// speedup vs baseline: 1.9604x; 1.9604x over previous
#include <cuda_runtime.h>
#include <math.h>
#include <stdint.h>

// ---------------- problem constants ----------------
#define BB     8
#define HH     128
#define WW     384
#define CC     192
#define NHEAD  6
#define WSZ    8
#define SSZ    4
#define HDIM   32
#define NWIN   768                 // windows per batch image (16*48)
#define NTOK   64                  // tokens per window
#define HWSZ   (HH*WW)             // 49152
#define MTOK   (BB*HWSZ)           // 393216 total tokens
#define C3     (3*CC)              // 576
#define MLPH   (4*CC)              // 768
#define SCALE  0.1767766952966369f // 32^-0.5
#define MCHUNK (MTOK/4)            // 98304 rows per MLP chunk

// ---------------- scratch (device globals; ALIASED by live range) ---------
// Total 1.2GB (host shadow symbols must stay < 2GB or host link breaks).
__device__ float g_bufA[(size_t)MTOK * CC];   // win -> att -> mlp chunk
__device__ float g_bufB[(size_t)MTOK * C3];   // qkv -> (x1 | h2)

// window-layout row m -> original token index (same map for gather & scatter)
__device__ __forceinline__ int win_to_tok(int m) {
    int b  = m / HWSZ;
    int r  = m - b * HWSZ;
    int w  = r >> 6;
    int nt = r & 63;
    int wrow = w / 48;
    int wcol = w - wrow * 48;
    int sh = (wrow << 3) + (nt >> 3);
    int sw = (wcol << 3) + (nt & 7);
    int fh = (sh + SSZ) & (HH - 1);
    int fw = sw + SSZ; if (fw >= WW) fw -= WW;
    return b * HWSZ + fh * WW + fw;
}

// ---------------- LayerNorm (one warp per token) --------------------------
template<bool GATHER>
__global__ void ln_kernel(const float* __restrict__ x,
                          const float* __restrict__ gamma,
                          const float* __restrict__ beta,
                          float* __restrict__ out) {
    int warp = blockIdx.x * (blockDim.x >> 5) + (threadIdx.x >> 5);
    if (warp >= MTOK) return;
    int lane = threadIdx.x & 31;
    int src = GATHER ? win_to_tok(warp) : warp;
    const float* xr = x + (size_t)src * CC;
    float v[6], s = 0.f, ss = 0.f;
#pragma unroll
    for (int i = 0; i < 6; i++) {
        float t = xr[lane + i * 32];
        v[i] = t; s += t; ss += t * t;
    }
#pragma unroll
    for (int o = 16; o; o >>= 1) {
        s  += __shfl_xor_sync(0xffffffffu, s,  o);
        ss += __shfl_xor_sync(0xffffffffu, ss, o);
    }
    float mean = s * (1.f / CC);
    float var  = ss * (1.f / CC) - mean * mean;
    float rstd = rsqrtf(var + 1e-5f);
    float* orow = out + (size_t)warp * CC;
#pragma unroll
    for (int i = 0; i < 6; i++) {
        int c = lane + i * 32;
        orow[c] = (v[i] - mean) * rstd * gamma[c] + beta[c];
    }
}

// ---------------- TF32 tensor-core GEMM -----------------------------------
// out[m,n] = sum_k A[m,k]*W[n,k] (+epilogue). A row-major [M,K], W row-major
// [N,K]. BM=128 BN=64 BK=16, 256 threads = 8 warps (4x2), warp tile 32x32 =
// 2x4 m16n8k8 MMAs x 2 k-steps. Smem stride 20 words -> conflict-free
// fragment loads ((20*row + k) mod 32 hits 32 distinct banks).
#define EPI_BIAS 0
#define EPI_PROJ 1
#define EPI_GELU 2
#define EPI_RES  3

__device__ __forceinline__ uint32_t f2tf(float x) {
    uint32_t r; asm("cvt.rna.tf32.f32 %0, %1;" : "=r"(r) : "f"(x)); return r;
}

__device__ __forceinline__ void mma_tf32(float c[4],
        uint32_t a0, uint32_t a1, uint32_t a2, uint32_t a3,
        uint32_t b0, uint32_t b1) {
    asm volatile(
        "mma.sync.aligned.m16n8k8.row.col.f32.tf32.tf32.f32 "
        "{%0,%1,%2,%3},{%4,%5,%6,%7},{%8,%9},{%0,%1,%2,%3};"
        : "+f"(c[0]), "+f"(c[1]), "+f"(c[2]), "+f"(c[3])
        : "r"(a0), "r"(a1), "r"(a2), "r"(a3), "r"(b0), "r"(b1));
}

template<int EPI>
__global__ __launch_bounds__(256)
void gemm_tc(const float* __restrict__ A, const float* __restrict__ W,
             const float* __restrict__ bias, const float* __restrict__ res,
             float* __restrict__ out, int M, int N, int K) {
    __shared__ uint32_t As[128][20];   // [m][k], stride 20
    __shared__ uint32_t Bs[64][20];    // [n][k], stride 20

    int tid  = threadIdx.x;
    int lane = tid & 31, warp = tid >> 5;
    int grp  = lane >> 2, tig = lane & 3;
    int m0 = blockIdx.y * 128, n0 = blockIdx.x * 64;
    int wm = (warp & 3) * 32;          // warp M base in tile
    int wn = (warp >> 2) * 32;         // warp N base in tile
    int ldRow = tid >> 2;              // 0..63
    int ldCol = (tid & 3) << 2;        // 0,4,8,12

    float acc[2][4][4] = {};

    for (int k0 = 0; k0 < K; k0 += 16) {
#pragma unroll
        for (int r = 0; r < 128; r += 64) {
            float4 t = *(const float4*)(A + (size_t)(m0 + ldRow + r) * K + k0 + ldCol);
            uint4 u = { f2tf(t.x), f2tf(t.y), f2tf(t.z), f2tf(t.w) };
            *(uint4*)&As[ldRow + r][ldCol] = u;
        }
        {
            float4 t = *(const float4*)(W + (size_t)(n0 + ldRow) * K + k0 + ldCol);
            uint4 u = { f2tf(t.x), f2tf(t.y), f2tf(t.z), f2tf(t.w) };
            *(uint4*)&Bs[ldRow][ldCol] = u;
        }
        __syncthreads();

#pragma unroll
        for (int ks = 0; ks < 2; ks++) {
            int kb = ks * 8;
            uint32_t a[2][4], b[4][2];
#pragma unroll
            for (int i = 0; i < 2; i++) {
                int r = wm + i * 16 + grp;
                a[i][0] = As[r    ][kb + tig];
                a[i][1] = As[r + 8][kb + tig];
                a[i][2] = As[r    ][kb + tig + 4];
                a[i][3] = As[r + 8][kb + tig + 4];
            }
#pragma unroll
            for (int j = 0; j < 4; j++) {
                int n = wn + j * 8 + grp;
                b[j][0] = Bs[n][kb + tig];
                b[j][1] = Bs[n][kb + tig + 4];
            }
#pragma unroll
            for (int i = 0; i < 2; i++)
#pragma unroll
                for (int j = 0; j < 4; j++)
                    mma_tf32(acc[i][j], a[i][0], a[i][1], a[i][2], a[i][3],
                             b[j][0], b[j][1]);
        }
        __syncthreads();
    }

    // epilogue: c0/c1 -> row grp, cols 2tig/2tig+1; c2/c3 -> row grp+8
#pragma unroll
    for (int i = 0; i < 2; i++) {
#pragma unroll
        for (int h = 0; h < 2; h++) {
            int m = m0 + wm + i * 16 + grp + h * 8;
            int dst = (EPI == EPI_PROJ) ? win_to_tok(m) : m;
#pragma unroll
            for (int j = 0; j < 4; j++) {
                int n = n0 + wn + j * 8 + 2 * tig;
                float v0 = acc[i][j][h * 2 + 0] + bias[n];
                float v1 = acc[i][j][h * 2 + 1] + bias[n + 1];
                size_t oi = (size_t)dst * N + n;
                if (EPI == EPI_GELU) {
                    v0 = 0.5f * v0 * (1.f + erff(v0 * 0.70710678118654752f));
                    v1 = 0.5f * v1 * (1.f + erff(v1 * 0.70710678118654752f));
                } else if (EPI == EPI_PROJ || EPI == EPI_RES) {
                    float2 rv = *(const float2*)(res + oi);
                    v0 += rv.x; v1 += rv.y;
                }
                float2 o = { v0, v1 };
                *(float2*)(out + oi) = o;
            }
        }
    }
}

// ---------------- windowed attention: one block per (window, head) --------
__global__ __launch_bounds__(128)
void attn_kernel(const float* __restrict__ qkv,
                 const float* __restrict__ rpb,      // [225, 6]
                 const int*   __restrict__ rel_idx,  // [64*64]
                 const float* __restrict__ mask,     // [768, 64, 64]
                 float* __restrict__ out) {          // [M, 192] window layout
    __shared__ float q[NTOK][HDIM];
    __shared__ float k[NTOK][HDIM + 1];
    __shared__ float v[NTOK][HDIM];
    __shared__ float S[NTOK][NTOK + 1];

    int wg   = blockIdx.x;
    int head = blockIdx.y;
    int tid  = threadIdx.x;

    const float* base = qkv + (size_t)wg * NTOK * C3 + head * HDIM;
    for (int idx = tid; idx < NTOK * HDIM; idx += 128) {
        int n = idx >> 5, d = idx & 31;
        const float* row = base + (size_t)n * C3 + d;
        q[n][d] = row[0];
        k[n][d] = row[CC];
        v[n][d] = row[2 * CC];
    }
    __syncthreads();

    const float* mrow = mask + (size_t)(wg % NWIN) * NTOK * NTOK;
    for (int e = tid; e < NTOK * NTOK; e += 128) {
        int n = e >> 6, mm = e & 63;
        float acc = 0.f;
#pragma unroll
        for (int d = 0; d < HDIM; d++) acc = fmaf(q[n][d], k[mm][d], acc);
        float bias = rpb[rel_idx[e] * NHEAD + head];
        S[n][mm] = acc * SCALE + bias + mrow[e];
    }
    __syncthreads();

    if (tid < NTOK) {
        float mx = -1e30f;
#pragma unroll 8
        for (int mm = 0; mm < NTOK; mm++) mx = fmaxf(mx, S[tid][mm]);
        float sum = 0.f;
#pragma unroll 8
        for (int mm = 0; mm < NTOK; mm++) {
            float e = expf(S[tid][mm] - mx);
            S[tid][mm] = e; sum += e;
        }
        float inv = 1.f / sum;
#pragma unroll 8
        for (int mm = 0; mm < NTOK; mm++) S[tid][mm] *= inv;
    }
    __syncthreads();

    float* orow = out + (size_t)wg * NTOK * CC + head * HDIM;
    for (int e = tid; e < NTOK * HDIM; e += 128) {
        int n = e >> 5, d = e & 31;
        float acc = 0.f;
#pragma unroll
        for (int mm = 0; mm < NTOK; mm++) acc = fmaf(S[n][mm], v[mm][d], acc);
        orow[(size_t)n * CC + d] = acc;
    }
}

// ---------------- launch ---------------------------------------------------
extern "C" void kernel_launch(void* const* d_in, const int* in_sizes, int n_in,
                              void* d_out, int out_size) {
    const float* x        = (const float*)d_in[0];
    const float* qkv_w    = (const float*)d_in[1];
    const float* qkv_b    = (const float*)d_in[2];
    const float* rpb      = (const float*)d_in[3];
    const float* proj_w   = (const float*)d_in[4];
    const float* proj_b   = (const float*)d_in[5];
    const float* g1       = (const float*)d_in[6];
    const float* b1       = (const float*)d_in[7];
    const float* g2       = (const float*)d_in[8];
    const float* b2       = (const float*)d_in[9];
    const float* fc1_w    = (const float*)d_in[10];
    const float* fc1_b    = (const float*)d_in[11];
    const float* fc2_w    = (const float*)d_in[12];
    const float* fc2_b    = (const float*)d_in[13];
    const int*   rel_idx  = (const int*)  d_in[14];
    const float* amask    = (const float*)d_in[15];
    float* out = (float*)d_out;

    float *bufA, *bufB;
    cudaGetSymbolAddress((void**)&bufA, g_bufA);
    cudaGetSymbolAddress((void**)&bufB, g_bufB);

    float* win  = bufA;
    float* qkvb = bufB;
    float* att  = bufA;                        // win dead
    float* x1   = bufB;                        // qkv dead
    float* h2   = bufB + (size_t)MTOK * CC;
    float* mlpc = bufA;                        // att dead

    const int LN_BLOCKS = MTOK / 8;

    // 1) LN1 + shift + window partition (gather)
    ln_kernel<true><<<LN_BLOCKS, 256>>>(x, g1, b1, win);

    // 2) QKV GEMM  [M,192] x [576,192]^T -> [M,576]
    gemm_tc<EPI_BIAS><<<dim3(C3 / 64, MTOK / 128), 256>>>(
        win, qkv_w, qkv_b, nullptr, qkvb, MTOK, C3, CC);

    // 3) attention per (window, head)
    attn_kernel<<<dim3(BB * NWIN, NHEAD), 128>>>(qkvb, rpb, rel_idx, amask, att);

    // 4) proj GEMM + window-reverse/unshift scatter + residual -> x1
    gemm_tc<EPI_PROJ><<<dim3(CC / 64, MTOK / 128), 256>>>(
        att, proj_w, proj_b, x, x1, MTOK, CC, CC);

    // 5) LN2
    ln_kernel<false><<<LN_BLOCKS, 256>>>(x1, g2, b2, h2);

    // 6/7) MLP in 4 row-chunks (scratch = MTOK*CC floats exactly)
    for (int c = 0; c < 4; c++) {
        size_t roff = (size_t)c * MCHUNK;
        gemm_tc<EPI_GELU><<<dim3(MLPH / 64, MCHUNK / 128), 256>>>(
            h2 + roff * CC, fc1_w, fc1_b, nullptr, mlpc, MCHUNK, MLPH, CC);
        gemm_tc<EPI_RES><<<dim3(CC / 64, MCHUNK / 128), 256>>>(
            mlpc, fc2_w, fc2_b, x1 + roff * CC, out + roff * CC,
            MCHUNK, CC, MLPH);
    }

    (void)in_sizes; (void)n_in; (void)out_size;
}

// round 5
// speedup vs baseline: 2.3002x; 1.1733x over previous
#include <cuda_runtime.h>
#include <math.h>
#include <stdint.h>

// ---------------- problem constants ----------------
#define BB     8
#define HH     128
#define WW     384
#define CC     192
#define NHEAD  6
#define WSZ    8
#define SSZ    4
#define HDIM   32
#define NWIN   768                 // windows per batch image (16*48)
#define NTOK   64                  // tokens per window
#define HWSZ   (HH*WW)             // 49152
#define MTOK   (BB*HWSZ)           // 393216 total tokens
#define C3     (3*CC)              // 576
#define MLPH   (4*CC)              // 768
#define SCALE  0.1767766952966369f // 32^-0.5
#define MCHUNK (MTOK/4)            // 98304 rows per MLP chunk

// ---------------- scratch (device globals; ALIASED by live range) ---------
// Total 1.2GB (host shadow symbols must stay < 2GB or host link breaks).
__device__ float g_bufA[(size_t)MTOK * CC];   // win -> att -> mlp chunk
__device__ float g_bufB[(size_t)MTOK * C3];   // qkv -> (x1 | h2)

// window-layout row m -> original token index (same map for gather & scatter)
__device__ __forceinline__ int win_to_tok(int m) {
    int b  = m / HWSZ;
    int r  = m - b * HWSZ;
    int w  = r >> 6;
    int nt = r & 63;
    int wrow = w / 48;
    int wcol = w - wrow * 48;
    int sh = (wrow << 3) + (nt >> 3);
    int sw = (wcol << 3) + (nt & 7);
    int fh = (sh + SSZ) & (HH - 1);
    int fw = sw + SSZ; if (fw >= WW) fw -= WW;
    return b * HWSZ + fh * WW + fw;
}

// ---------------- LayerNorm (one warp per token) --------------------------
template<bool GATHER>
__global__ void ln_kernel(const float* __restrict__ x,
                          const float* __restrict__ gamma,
                          const float* __restrict__ beta,
                          float* __restrict__ out) {
    int warp = blockIdx.x * (blockDim.x >> 5) + (threadIdx.x >> 5);
    if (warp >= MTOK) return;
    int lane = threadIdx.x & 31;
    int src = GATHER ? win_to_tok(warp) : warp;
    const float* xr = x + (size_t)src * CC;
    float v[6], s = 0.f, ss = 0.f;
#pragma unroll
    for (int i = 0; i < 6; i++) {
        float t = xr[lane + i * 32];
        v[i] = t; s += t; ss += t * t;
    }
#pragma unroll
    for (int o = 16; o; o >>= 1) {
        s  += __shfl_xor_sync(0xffffffffu, s,  o);
        ss += __shfl_xor_sync(0xffffffffu, ss, o);
    }
    float mean = s * (1.f / CC);
    float var  = ss * (1.f / CC) - mean * mean;
    float rstd = rsqrtf(var + 1e-5f);
    float* orow = out + (size_t)warp * CC;
#pragma unroll
    for (int i = 0; i < 6; i++) {
        int c = lane + i * 32;
        orow[c] = (v[i] - mean) * rstd * gamma[c] + beta[c];
    }
}

// ---------------- TF32 tensor-core GEMM (ldmatrix + cp.async) -------------
// out[m,n] = sum_k A[m,k]*W[n,k] (+epilogue). A row-major [M,K], W row-major
// [N,K]. BM=128 BN=64 BK=16, 256 threads = 8 warps (4x2), warp tile 32x32 =
// 2x4 m16n8k8 MMAs x 2 k-steps. Raw fp32 bits fed to HMMA.TF32 (hardware
// truncates to tf32 = RZ convert; the standard CUTLASS path). Stride-20 rows
// keep both LDSM octets and fills conflict-free. 2-stage cp.async pipeline.
#define EPI_BIAS 0
#define EPI_PROJ 1
#define EPI_GELU 2
#define EPI_RES  3

#define AW_STAGE (128*20)   // words per A stage
#define BW_STAGE (64*20)    // words per B stage

__device__ __forceinline__ void cp16(uint32_t s, const void* g) {
    asm volatile("cp.async.cg.shared.global [%0], [%1], 16;" :: "r"(s), "l"(g));
}
__device__ __forceinline__ void ldsm4(uint32_t* r, uint32_t addr) {
    asm volatile("ldmatrix.sync.aligned.m8n8.x4.shared.b16 {%0,%1,%2,%3}, [%4];"
        : "=r"(r[0]), "=r"(r[1]), "=r"(r[2]), "=r"(r[3]) : "r"(addr));
}
__device__ __forceinline__ void mma_tf32(float c[4],
        uint32_t a0, uint32_t a1, uint32_t a2, uint32_t a3,
        uint32_t b0, uint32_t b1) {
    asm volatile(
        "mma.sync.aligned.m16n8k8.row.col.f32.tf32.tf32.f32 "
        "{%0,%1,%2,%3},{%4,%5,%6,%7},{%8,%9},{%0,%1,%2,%3};"
        : "+f"(c[0]), "+f"(c[1]), "+f"(c[2]), "+f"(c[3])
        : "r"(a0), "r"(a1), "r"(a2), "r"(a3), "r"(b0), "r"(b1));
}

template<int EPI>
__global__ __launch_bounds__(256)
void gemm_tc(const float* __restrict__ A, const float* __restrict__ W,
             const float* __restrict__ bias, const float* __restrict__ res,
             float* __restrict__ out, int M, int N, int K) {
    __shared__ uint32_t As[2 * AW_STAGE];
    __shared__ uint32_t Bs[2 * BW_STAGE];

    int tid  = threadIdx.x;
    int lane = tid & 31, warp = tid >> 5;
    int grp  = lane >> 2, tig = lane & 3;
    int sub  = lane >> 3, tr8 = lane & 7;     // LDSM octet id / row-in-octet
    int m0 = blockIdx.y * 128, n0 = blockIdx.x * 64;
    int wm = (warp & 3) * 32;                 // warp M base
    int wn = (warp >> 2) * 32;                // warp N base
    int ldRow = tid >> 2;                     // 0..63
    int ldCol = (tid & 3) << 2;               // 0,4,8,12 (words)

    uint32_t sA = (uint32_t)__cvta_generic_to_shared(As);
    uint32_t sB = (uint32_t)__cvta_generic_to_shared(Bs);

    // LDSM row-address word offsets (within a stage)
    int rowAw[2], rowBw[2];
#pragma unroll
    for (int i = 0; i < 2; i++)
        rowAw[i] = (wm + i * 16 + (sub & 1) * 8 + tr8) * 20 + (sub >> 1) * 4;
#pragma unroll
    for (int jp = 0; jp < 2; jp++)
        rowBw[jp] = (wn + jp * 16 + (sub >> 1) * 8 + tr8) * 20 + (sub & 1) * 4;

    float acc[2][4][4] = {};
    const int niter = K >> 4;

    // async fill of stage (it&1) for k0 = it*16
#define ISSUE(it) do {                                                        \
        int s_ = (it) & 1; int k0_ = (it) << 4;                               \
        cp16(sA + 4u*(s_*AW_STAGE + ldRow*20 + ldCol),                        \
             A + (size_t)(m0 + ldRow) * K + k0_ + ldCol);                     \
        cp16(sA + 4u*(s_*AW_STAGE + (ldRow+64)*20 + ldCol),                   \
             A + (size_t)(m0 + ldRow + 64) * K + k0_ + ldCol);                \
        cp16(sB + 4u*(s_*BW_STAGE + ldRow*20 + ldCol),                        \
             W + (size_t)(n0 + ldRow) * K + k0_ + ldCol);                     \
        asm volatile("cp.async.commit_group;");                               \
    } while (0)

    ISSUE(0);
    for (int it = 0; it < niter; it++) {
        if (it + 1 < niter) {
            ISSUE(it + 1);
            asm volatile("cp.async.wait_group 1;");
        } else {
            asm volatile("cp.async.wait_group 0;");
        }
        __syncthreads();

        uint32_t baseA = sA + 4u * ((it & 1) * AW_STAGE);
        uint32_t baseB = sB + 4u * ((it & 1) * BW_STAGE);
#pragma unroll
        for (int ks = 0; ks < 2; ks++) {
            int kb = ks * 8;
            uint32_t a[2][4], b[2][4];
            ldsm4(a[0], baseA + 4u * (rowAw[0] + kb));
            ldsm4(a[1], baseA + 4u * (rowAw[1] + kb));
            ldsm4(b[0], baseB + 4u * (rowBw[0] + kb));
            ldsm4(b[1], baseB + 4u * (rowBw[1] + kb));
#pragma unroll
            for (int i = 0; i < 2; i++)
#pragma unroll
                for (int j = 0; j < 4; j++)
                    mma_tf32(acc[i][j], a[i][0], a[i][1], a[i][2], a[i][3],
                             b[j >> 1][(j & 1) * 2], b[j >> 1][(j & 1) * 2 + 1]);
        }
        __syncthreads();
    }
#undef ISSUE

    // epilogue: c0/c1 -> row grp, cols 2tig/2tig+1; c2/c3 -> row grp+8
#pragma unroll
    for (int i = 0; i < 2; i++) {
#pragma unroll
        for (int h = 0; h < 2; h++) {
            int m = m0 + wm + i * 16 + grp + h * 8;
            int dst = (EPI == EPI_PROJ) ? win_to_tok(m) : m;
#pragma unroll
            for (int j = 0; j < 4; j++) {
                int n = n0 + wn + j * 8 + 2 * tig;
                float v0 = acc[i][j][h * 2 + 0] + bias[n];
                float v1 = acc[i][j][h * 2 + 1] + bias[n + 1];
                size_t oi = (size_t)dst * N + n;
                if (EPI == EPI_GELU) {
                    v0 = 0.5f * v0 * (1.f + erff(v0 * 0.70710678118654752f));
                    v1 = 0.5f * v1 * (1.f + erff(v1 * 0.70710678118654752f));
                } else if (EPI == EPI_PROJ || EPI == EPI_RES) {
                    float2 rv = *(const float2*)(res + oi);
                    v0 += rv.x; v1 += rv.y;
                }
                float2 o = { v0, v1 };
                *(float2*)(out + oi) = o;
            }
        }
    }
}

// ---------------- windowed attention: one block per (window, head) --------
__global__ __launch_bounds__(128)
void attn_kernel(const float* __restrict__ qkv,
                 const float* __restrict__ rpb,      // [225, 6]
                 const int*   __restrict__ rel_idx,  // [64*64]
                 const float* __restrict__ mask,     // [768, 64, 64]
                 float* __restrict__ out) {          // [M, 192] window layout
    __shared__ float q[NTOK][HDIM];
    __shared__ float k[NTOK][HDIM + 1];
    __shared__ float v[NTOK][HDIM];
    __shared__ float S[NTOK][NTOK + 1];

    int wg   = blockIdx.x;
    int head = blockIdx.y;
    int tid  = threadIdx.x;

    const float* base = qkv + (size_t)wg * NTOK * C3 + head * HDIM;
    for (int idx = tid; idx < NTOK * HDIM; idx += 128) {
        int n = idx >> 5, d = idx & 31;
        const float* row = base + (size_t)n * C3 + d;
        q[n][d] = row[0];
        k[n][d] = row[CC];
        v[n][d] = row[2 * CC];
    }
    __syncthreads();

    const float* mrow = mask + (size_t)(wg % NWIN) * NTOK * NTOK;
    for (int e = tid; e < NTOK * NTOK; e += 128) {
        int n = e >> 6, mm = e & 63;
        float acc = 0.f;
#pragma unroll
        for (int d = 0; d < HDIM; d++) acc = fmaf(q[n][d], k[mm][d], acc);
        float bias = rpb[rel_idx[e] * NHEAD + head];
        S[n][mm] = acc * SCALE + bias + mrow[e];
    }
    __syncthreads();

    if (tid < NTOK) {
        float mx = -1e30f;
#pragma unroll 8
        for (int mm = 0; mm < NTOK; mm++) mx = fmaxf(mx, S[tid][mm]);
        float sum = 0.f;
#pragma unroll 8
        for (int mm = 0; mm < NTOK; mm++) {
            float e = expf(S[tid][mm] - mx);
            S[tid][mm] = e; sum += e;
        }
        float inv = 1.f / sum;
#pragma unroll 8
        for (int mm = 0; mm < NTOK; mm++) S[tid][mm] *= inv;
    }
    __syncthreads();

    float* orow = out + (size_t)wg * NTOK * CC + head * HDIM;
    for (int e = tid; e < NTOK * HDIM; e += 128) {
        int n = e >> 5, d = e & 31;
        float acc = 0.f;
#pragma unroll
        for (int mm = 0; mm < NTOK; mm++) acc = fmaf(S[n][mm], v[mm][d], acc);
        orow[(size_t)n * CC + d] = acc;
    }
}

// ---------------- launch ---------------------------------------------------
extern "C" void kernel_launch(void* const* d_in, const int* in_sizes, int n_in,
                              void* d_out, int out_size) {
    const float* x        = (const float*)d_in[0];
    const float* qkv_w    = (const float*)d_in[1];
    const float* qkv_b    = (const float*)d_in[2];
    const float* rpb      = (const float*)d_in[3];
    const float* proj_w   = (const float*)d_in[4];
    const float* proj_b   = (const float*)d_in[5];
    const float* g1       = (const float*)d_in[6];
    const float* b1       = (const float*)d_in[7];
    const float* g2       = (const float*)d_in[8];
    const float* b2       = (const float*)d_in[9];
    const float* fc1_w    = (const float*)d_in[10];
    const float* fc1_b    = (const float*)d_in[11];
    const float* fc2_w    = (const float*)d_in[12];
    const float* fc2_b    = (const float*)d_in[13];
    const int*   rel_idx  = (const int*)  d_in[14];
    const float* amask    = (const float*)d_in[15];
    float* out = (float*)d_out;

    float *bufA, *bufB;
    cudaGetSymbolAddress((void**)&bufA, g_bufA);
    cudaGetSymbolAddress((void**)&bufB, g_bufB);

    float* win  = bufA;
    float* qkvb = bufB;
    float* att  = bufA;                        // win dead
    float* x1   = bufB;                        // qkv dead
    float* h2   = bufB + (size_t)MTOK * CC;
    float* mlpc = bufA;                        // att dead

    const int LN_BLOCKS = MTOK / 8;

    // 1) LN1 + shift + window partition (gather)
    ln_kernel<true><<<LN_BLOCKS, 256>>>(x, g1, b1, win);

    // 2) QKV GEMM  [M,192] x [576,192]^T -> [M,576]
    gemm_tc<EPI_BIAS><<<dim3(C3 / 64, MTOK / 128), 256>>>(
        win, qkv_w, qkv_b, nullptr, qkvb, MTOK, C3, CC);

    // 3) attention per (window, head)
    attn_kernel<<<dim3(BB * NWIN, NHEAD), 128>>>(qkvb, rpb, rel_idx, amask, att);

    // 4) proj GEMM + window-reverse/unshift scatter + residual -> x1
    gemm_tc<EPI_PROJ><<<dim3(CC / 64, MTOK / 128), 256>>>(
        att, proj_w, proj_b, x, x1, MTOK, CC, CC);

    // 5) LN2
    ln_kernel<false><<<LN_BLOCKS, 256>>>(x1, g2, b2, h2);

    // 6/7) MLP in 4 row-chunks (scratch = MTOK*CC floats exactly)
    for (int c = 0; c < 4; c++) {
        size_t roff = (size_t)c * MCHUNK;
        gemm_tc<EPI_GELU><<<dim3(MLPH / 64, MCHUNK / 128), 256>>>(
            h2 + roff * CC, fc1_w, fc1_b, nullptr, mlpc, MCHUNK, MLPH, CC);
        gemm_tc<EPI_RES><<<dim3(CC / 64, MCHUNK / 128), 256>>>(
            mlpc, fc2_w, fc2_b, x1 + roff * CC, out + roff * CC,
            MCHUNK, CC, MLPH);
    }

    (void)in_sizes; (void)n_in; (void)out_size;
}

// round 6
// speedup vs baseline: 2.4487x; 1.0646x over previous
#include <cuda_runtime.h>
#include <math.h>
#include <stdint.h>

// ---------------- problem constants ----------------
#define BB     8
#define HH     128
#define WW     384
#define CC     192
#define NHEAD  6
#define WSZ    8
#define SSZ    4
#define HDIM   32
#define NWIN   768                 // windows per batch image (16*48)
#define NTOK   64                  // tokens per window
#define HWSZ   (HH*WW)             // 49152
#define MTOK   (BB*HWSZ)           // 393216 total tokens
#define C3     (3*CC)              // 576
#define MLPH   (4*CC)              // 768
#define SCALE  0.1767766952966369f // 32^-0.5
#define MCHUNK (MTOK/4)            // 98304 rows per MLP chunk

// ---------------- scratch (device globals; ALIASED by live range) ---------
// Total 1.2GB (host shadow symbols must stay < 2GB or host link breaks).
__device__ float g_bufA[(size_t)MTOK * CC];   // win -> att -> mlp chunk
__device__ float g_bufB[(size_t)MTOK * C3];   // qkv -> (x1 | h2)

// window-layout row m -> original token index (same map for gather & scatter)
__device__ __forceinline__ int win_to_tok(int m) {
    int b  = m / HWSZ;
    int r  = m - b * HWSZ;
    int w  = r >> 6;
    int nt = r & 63;
    int wrow = w / 48;
    int wcol = w - wrow * 48;
    int sh = (wrow << 3) + (nt >> 3);
    int sw = (wcol << 3) + (nt & 7);
    int fh = (sh + SSZ) & (HH - 1);
    int fw = sw + SSZ; if (fw >= WW) fw -= WW;
    return b * HWSZ + fh * WW + fw;
}

// ---------------- LayerNorm (one warp per token) --------------------------
template<bool GATHER>
__global__ void ln_kernel(const float* __restrict__ x,
                          const float* __restrict__ gamma,
                          const float* __restrict__ beta,
                          float* __restrict__ out) {
    int warp = blockIdx.x * (blockDim.x >> 5) + (threadIdx.x >> 5);
    if (warp >= MTOK) return;
    int lane = threadIdx.x & 31;
    int src = GATHER ? win_to_tok(warp) : warp;
    const float* xr = x + (size_t)src * CC;
    float v[6], s = 0.f, ss = 0.f;
#pragma unroll
    for (int i = 0; i < 6; i++) {
        float t = xr[lane + i * 32];
        v[i] = t; s += t; ss += t * t;
    }
#pragma unroll
    for (int o = 16; o; o >>= 1) {
        s  += __shfl_xor_sync(0xffffffffu, s,  o);
        ss += __shfl_xor_sync(0xffffffffu, ss, o);
    }
    float mean = s * (1.f / CC);
    float var  = ss * (1.f / CC) - mean * mean;
    float rstd = rsqrtf(var + 1e-5f);
    float* orow = out + (size_t)warp * CC;
#pragma unroll
    for (int i = 0; i < 6; i++) {
        int c = lane + i * 32;
        orow[c] = (v[i] - mean) * rstd * gamma[c] + beta[c];
    }
}

// ---------------- TF32 tensor-core GEMM (3-stage multistage) --------------
// out[m,n] = sum_k A[m,k]*W[n,k] (+epilogue). A row-major [M,K], W row-major
// [N,K]. BM=128 BN=64 BK=16, 256 threads = 8 warps (4x2), warp tile 32x32 =
// 2x4 m16n8k8 MMAs x 2 k-steps. Raw fp32 bits fed to HMMA.TF32 (hw truncate).
// 3-stage cp.async ring, prefetch depth 2, ONE __syncthreads per iteration
// (fills issued AFTER the sync, so the overwritten slot — consumed in the
// previous iteration — is provably drained by all warps). 45KB static smem.
#define EPI_BIAS 0
#define EPI_PROJ 1
#define EPI_GELU 2
#define EPI_RES  3

#define NSTAGE   3
#define AW_STAGE (128*20)   // words per A stage
#define BW_STAGE (64*20)    // words per B stage

__device__ __forceinline__ void cp16(uint32_t s, const void* g) {
    asm volatile("cp.async.cg.shared.global [%0], [%1], 16;" :: "r"(s), "l"(g));
}
__device__ __forceinline__ void ldsm4(uint32_t* r, uint32_t addr) {
    asm volatile("ldmatrix.sync.aligned.m8n8.x4.shared.b16 {%0,%1,%2,%3}, [%4];"
        : "=r"(r[0]), "=r"(r[1]), "=r"(r[2]), "=r"(r[3]) : "r"(addr));
}
__device__ __forceinline__ void mma_tf32(float c[4],
        uint32_t a0, uint32_t a1, uint32_t a2, uint32_t a3,
        uint32_t b0, uint32_t b1) {
    asm volatile(
        "mma.sync.aligned.m16n8k8.row.col.f32.tf32.tf32.f32 "
        "{%0,%1,%2,%3},{%4,%5,%6,%7},{%8,%9},{%0,%1,%2,%3};"
        : "+f"(c[0]), "+f"(c[1]), "+f"(c[2]), "+f"(c[3])
        : "r"(a0), "r"(a1), "r"(a2), "r"(a3), "r"(b0), "r"(b1));
}

template<int EPI>
__global__ __launch_bounds__(256)
void gemm_tc(const float* __restrict__ A, const float* __restrict__ W,
             const float* __restrict__ bias, const float* __restrict__ res,
             float* __restrict__ out, int M, int N, int K) {
    __shared__ uint32_t As[NSTAGE * AW_STAGE];
    __shared__ uint32_t Bs[NSTAGE * BW_STAGE];

    int tid  = threadIdx.x;
    int lane = tid & 31, warp = tid >> 5;
    int grp  = lane >> 2, tig = lane & 3;
    int sub  = lane >> 3, tr8 = lane & 7;     // LDSM octet id / row-in-octet
    int m0 = blockIdx.y * 128, n0 = blockIdx.x * 64;
    int wm = (warp & 3) * 32;                 // warp M base
    int wn = (warp >> 2) * 32;                // warp N base
    int ldRow = tid >> 2;                     // 0..63
    int ldCol = (tid & 3) << 2;               // 0,4,8,12 (words)

    uint32_t sA = (uint32_t)__cvta_generic_to_shared(As);
    uint32_t sB = (uint32_t)__cvta_generic_to_shared(Bs);

    // LDSM row-address word offsets (within a stage)
    int rowAw[2], rowBw[2];
#pragma unroll
    for (int i = 0; i < 2; i++)
        rowAw[i] = (wm + i * 16 + (sub & 1) * 8 + tr8) * 20 + (sub >> 1) * 4;
#pragma unroll
    for (int jp = 0; jp < 2; jp++)
        rowBw[jp] = (wn + jp * 16 + (sub >> 1) * 8 + tr8) * 20 + (sub & 1) * 4;

    float acc[2][4][4] = {};
    const int niter = K >> 4;

    // async fill of stage slot (it % NSTAGE) for k0 = it*16
#define ISSUE(it) do {                                                        \
        int s_ = (it) % NSTAGE; int k0_ = (it) << 4;                          \
        cp16(sA + 4u*(s_*AW_STAGE + ldRow*20 + ldCol),                        \
             A + (size_t)(m0 + ldRow) * K + k0_ + ldCol);                     \
        cp16(sA + 4u*(s_*AW_STAGE + (ldRow+64)*20 + ldCol),                   \
             A + (size_t)(m0 + ldRow + 64) * K + k0_ + ldCol);                \
        cp16(sB + 4u*(s_*BW_STAGE + ldRow*20 + ldCol),                        \
             W + (size_t)(n0 + ldRow) * K + k0_ + ldCol);                     \
    } while (0)

    // prologue: prefetch stages 0,1 (one commit group each)
    ISSUE(0); asm volatile("cp.async.commit_group;");
    if (niter > 1) { ISSUE(1); }
    asm volatile("cp.async.commit_group;");

    for (int it = 0; it < niter; it++) {
        // stage `it` complete when <=1 groups outstanding
        asm volatile("cp.async.wait_group 1;");
        __syncthreads();
        // fill stage it+2 (slot (it-1)%3, drained by every warp before this sync)
        if (it + 2 < niter) { ISSUE(it + 2); }
        asm volatile("cp.async.commit_group;");

        uint32_t baseA = sA + 4u * ((it % NSTAGE) * AW_STAGE);
        uint32_t baseB = sB + 4u * ((it % NSTAGE) * BW_STAGE);
#pragma unroll
        for (int ks = 0; ks < 2; ks++) {
            int kb = ks * 8;
            uint32_t a[2][4], b[2][4];
            ldsm4(a[0], baseA + 4u * (rowAw[0] + kb));
            ldsm4(a[1], baseA + 4u * (rowAw[1] + kb));
            ldsm4(b[0], baseB + 4u * (rowBw[0] + kb));
            ldsm4(b[1], baseB + 4u * (rowBw[1] + kb));
#pragma unroll
            for (int i = 0; i < 2; i++)
#pragma unroll
                for (int j = 0; j < 4; j++)
                    mma_tf32(acc[i][j], a[i][0], a[i][1], a[i][2], a[i][3],
                             b[j >> 1][(j & 1) * 2], b[j >> 1][(j & 1) * 2 + 1]);
        }
    }
#undef ISSUE

    // epilogue: c0/c1 -> row grp, cols 2tig/2tig+1; c2/c3 -> row grp+8
#pragma unroll
    for (int i = 0; i < 2; i++) {
#pragma unroll
        for (int h = 0; h < 2; h++) {
            int m = m0 + wm + i * 16 + grp + h * 8;
            int dst = (EPI == EPI_PROJ) ? win_to_tok(m) : m;
#pragma unroll
            for (int j = 0; j < 4; j++) {
                int n = n0 + wn + j * 8 + 2 * tig;
                float v0 = acc[i][j][h * 2 + 0] + bias[n];
                float v1 = acc[i][j][h * 2 + 1] + bias[n + 1];
                size_t oi = (size_t)dst * N + n;
                if (EPI == EPI_GELU) {
                    v0 = 0.5f * v0 * (1.f + erff(v0 * 0.70710678118654752f));
                    v1 = 0.5f * v1 * (1.f + erff(v1 * 0.70710678118654752f));
                } else if (EPI == EPI_PROJ || EPI == EPI_RES) {
                    float2 rv = *(const float2*)(res + oi);
                    v0 += rv.x; v1 += rv.y;
                }
                float2 o = { v0, v1 };
                *(float2*)(out + oi) = o;
            }
        }
    }
}

// ---------------- windowed attention: one block per (window, head) --------
__global__ __launch_bounds__(128)
void attn_kernel(const float* __restrict__ qkv,
                 const float* __restrict__ rpb,      // [225, 6]
                 const int*   __restrict__ rel_idx,  // [64*64]
                 const float* __restrict__ mask,     // [768, 64, 64]
                 float* __restrict__ out) {          // [M, 192] window layout
    __shared__ float q[NTOK][HDIM];
    __shared__ float k[NTOK][HDIM + 1];
    __shared__ float v[NTOK][HDIM];
    __shared__ float S[NTOK][NTOK + 1];

    int wg   = blockIdx.x;
    int head = blockIdx.y;
    int tid  = threadIdx.x;

    const float* base = qkv + (size_t)wg * NTOK * C3 + head * HDIM;
    for (int idx = tid; idx < NTOK * HDIM; idx += 128) {
        int n = idx >> 5, d = idx & 31;
        const float* row = base + (size_t)n * C3 + d;
        q[n][d] = row[0];
        k[n][d] = row[CC];
        v[n][d] = row[2 * CC];
    }
    __syncthreads();

    const float* mrow = mask + (size_t)(wg % NWIN) * NTOK * NTOK;
    for (int e = tid; e < NTOK * NTOK; e += 128) {
        int n = e >> 6, mm = e & 63;
        float acc = 0.f;
#pragma unroll
        for (int d = 0; d < HDIM; d++) acc = fmaf(q[n][d], k[mm][d], acc);
        float bias = rpb[rel_idx[e] * NHEAD + head];
        S[n][mm] = acc * SCALE + bias + mrow[e];
    }
    __syncthreads();

    if (tid < NTOK) {
        float mx = -1e30f;
#pragma unroll 8
        for (int mm = 0; mm < NTOK; mm++) mx = fmaxf(mx, S[tid][mm]);
        float sum = 0.f;
#pragma unroll 8
        for (int mm = 0; mm < NTOK; mm++) {
            float e = expf(S[tid][mm] - mx);
            S[tid][mm] = e; sum += e;
        }
        float inv = 1.f / sum;
#pragma unroll 8
        for (int mm = 0; mm < NTOK; mm++) S[tid][mm] *= inv;
    }
    __syncthreads();

    float* orow = out + (size_t)wg * NTOK * CC + head * HDIM;
    for (int e = tid; e < NTOK * HDIM; e += 128) {
        int n = e >> 5, d = e & 31;
        float acc = 0.f;
#pragma unroll
        for (int mm = 0; mm < NTOK; mm++) acc = fmaf(S[n][mm], v[mm][d], acc);
        orow[(size_t)n * CC + d] = acc;
    }
}

// ---------------- launch ---------------------------------------------------
extern "C" void kernel_launch(void* const* d_in, const int* in_sizes, int n_in,
                              void* d_out, int out_size) {
    const float* x        = (const float*)d_in[0];
    const float* qkv_w    = (const float*)d_in[1];
    const float* qkv_b    = (const float*)d_in[2];
    const float* rpb      = (const float*)d_in[3];
    const float* proj_w   = (const float*)d_in[4];
    const float* proj_b   = (const float*)d_in[5];
    const float* g1       = (const float*)d_in[6];
    const float* b1       = (const float*)d_in[7];
    const float* g2       = (const float*)d_in[8];
    const float* b2       = (const float*)d_in[9];
    const float* fc1_w    = (const float*)d_in[10];
    const float* fc1_b    = (const float*)d_in[11];
    const float* fc2_w    = (const float*)d_in[12];
    const float* fc2_b    = (const float*)d_in[13];
    const int*   rel_idx  = (const int*)  d_in[14];
    const float* amask    = (const float*)d_in[15];
    float* out = (float*)d_out;

    float *bufA, *bufB;
    cudaGetSymbolAddress((void**)&bufA, g_bufA);
    cudaGetSymbolAddress((void**)&bufB, g_bufB);

    float* win  = bufA;
    float* qkvb = bufB;
    float* att  = bufA;                        // win dead
    float* x1   = bufB;                        // qkv dead
    float* h2   = bufB + (size_t)MTOK * CC;
    float* mlpc = bufA;                        // att dead

    const int LN_BLOCKS = MTOK / 8;

    // 1) LN1 + shift + window partition (gather)
    ln_kernel<true><<<LN_BLOCKS, 256>>>(x, g1, b1, win);

    // 2) QKV GEMM  [M,192] x [576,192]^T -> [M,576]
    gemm_tc<EPI_BIAS><<<dim3(C3 / 64, MTOK / 128), 256>>>(
        win, qkv_w, qkv_b, nullptr, qkvb, MTOK, C3, CC);

    // 3) attention per (window, head)
    attn_kernel<<<dim3(BB * NWIN, NHEAD), 128>>>(qkvb, rpb, rel_idx, amask, att);

    // 4) proj GEMM + window-reverse/unshift scatter + residual -> x1
    gemm_tc<EPI_PROJ><<<dim3(CC / 64, MTOK / 128), 256>>>(
        att, proj_w, proj_b, x, x1, MTOK, CC, CC);

    // 5) LN2
    ln_kernel<false><<<LN_BLOCKS, 256>>>(x1, g2, b2, h2);

    // 6/7) MLP in 4 row-chunks (scratch = MTOK*CC floats exactly)
    for (int c = 0; c < 4; c++) {
        size_t roff = (size_t)c * MCHUNK;
        gemm_tc<EPI_GELU><<<dim3(MLPH / 64, MCHUNK / 128), 256>>>(
            h2 + roff * CC, fc1_w, fc1_b, nullptr, mlpc, MCHUNK, MLPH, CC);
        gemm_tc<EPI_RES><<<dim3(CC / 64, MCHUNK / 128), 256>>>(
            mlpc, fc2_w, fc2_b, x1 + roff * CC, out + roff * CC,
            MCHUNK, CC, MLPH);
    }

    (void)in_sizes; (void)n_in; (void)out_size;
}

// round 8
// speedup vs baseline: 2.5965x; 1.0604x over previous
#include <cuda_runtime.h>
#include <math.h>
#include <stdint.h>

// ---------------- problem constants ----------------
#define BB     8
#define HH     128
#define WW     384
#define CC     192
#define NHEAD  6
#define WSZ    8
#define SSZ    4
#define HDIM   32
#define NWIN   768
#define NTOK   64
#define HWSZ   (HH*WW)             // 49152
#define MTOK   (BB*HWSZ)           // 393216
#define C3     (3*CC)              // 576
#define MLPH   (4*CC)              // 768
#define SCALE  0.1767766952966369f
#define MCHUNK (MTOK/4)            // 98304

// ---------------- scratch (aliased; keep <2GB total for host link) --------
__device__ float g_bufA[(size_t)MTOK * CC];   // win -> att -> mlp chunk
__device__ float g_bufB[(size_t)MTOK * C3];   // qkv -> (x1 | h2)
__device__ float g_biasT[NHEAD * NTOK * NTOK]; // rpb[rel_idx] pre-gathered

__device__ __forceinline__ int win_to_tok(int m) {
    int b  = m / HWSZ;
    int r  = m - b * HWSZ;
    int w  = r >> 6;
    int nt = r & 63;
    int wrow = w / 48;
    int wcol = w - wrow * 48;
    int sh = (wrow << 3) + (nt >> 3);
    int sw = (wcol << 3) + (nt & 7);
    int fh = (sh + SSZ) & (HH - 1);
    int fw = sw + SSZ; if (fw >= WW) fw -= WW;
    return b * HWSZ + fh * WW + fw;
}

// ---------------- LayerNorm (one warp per token) --------------------------
template<bool GATHER>
__global__ void ln_kernel(const float* __restrict__ x,
                          const float* __restrict__ gamma,
                          const float* __restrict__ beta,
                          float* __restrict__ out) {
    int warp = blockIdx.x * (blockDim.x >> 5) + (threadIdx.x >> 5);
    if (warp >= MTOK) return;
    int lane = threadIdx.x & 31;
    int src = GATHER ? win_to_tok(warp) : warp;
    const float* xr = x + (size_t)src * CC;
    float v[6], s = 0.f, ss = 0.f;
#pragma unroll
    for (int i = 0; i < 6; i++) {
        float t = xr[lane + i * 32];
        v[i] = t; s += t; ss += t * t;
    }
#pragma unroll
    for (int o = 16; o; o >>= 1) {
        s  += __shfl_xor_sync(0xffffffffu, s,  o);
        ss += __shfl_xor_sync(0xffffffffu, ss, o);
    }
    float mean = s * (1.f / CC);
    float var  = ss * (1.f / CC) - mean * mean;
    float rstd = rsqrtf(var + 1e-5f);
    float* orow = out + (size_t)warp * CC;
#pragma unroll
    for (int i = 0; i < 6; i++) {
        int c = lane + i * 32;
        orow[c] = (v[i] - mean) * rstd * gamma[c] + beta[c];
    }
}

// ---------------- bias pre-gather: biasT[h][e] = rpb[rel_idx[e]][h] -------
__global__ void bias_gather_kernel(const float* __restrict__ rpb,
                                   const int* __restrict__ rel_idx,
                                   float* __restrict__ biasT) {
    int i = blockIdx.x * blockDim.x + threadIdx.x;
    if (i >= NHEAD * NTOK * NTOK) return;
    int h = i / (NTOK * NTOK), e = i % (NTOK * NTOK);
    biasT[i] = rpb[rel_idx[e] * NHEAD + h];
}

// ---------------- TF32 mma GEMM, BM=256 BN=64 BK=16, 3-stage --------------
// out[m,n] = sum_k A[m,k]*W[n,k] (+epilogue). 256 threads = 8 warps (4Mx2N),
// warp tile 64x32 = 4x4 m16n8k8 MMAs x 2 k-steps. Raw fp32 bits -> HMMA.TF32.
// 3-stage cp.async ring, one __syncthreads per iter. 76.8KB dynamic smem.
#define EPI_BIAS 0
#define EPI_PROJ 1
#define EPI_GELU 2
#define EPI_RES  3

#define NSTAGE   3
#define AW_STAGE (256*20)   // words per A stage
#define BW_STAGE (64*20)    // words per B stage
#define SMEM_DYN (NSTAGE * (AW_STAGE + BW_STAGE) * 4)

__device__ __forceinline__ void cp16(uint32_t s, const void* g) {
    asm volatile("cp.async.cg.shared.global [%0], [%1], 16;" :: "r"(s), "l"(g));
}
__device__ __forceinline__ void ldsm4(uint32_t* r, uint32_t addr) {
    asm volatile("ldmatrix.sync.aligned.m8n8.x4.shared.b16 {%0,%1,%2,%3}, [%4];"
        : "=r"(r[0]), "=r"(r[1]), "=r"(r[2]), "=r"(r[3]) : "r"(addr));
}
__device__ __forceinline__ void mma_tf32(float c[4],
        uint32_t a0, uint32_t a1, uint32_t a2, uint32_t a3,
        uint32_t b0, uint32_t b1) {
    asm volatile(
        "mma.sync.aligned.m16n8k8.row.col.f32.tf32.tf32.f32 "
        "{%0,%1,%2,%3},{%4,%5,%6,%7},{%8,%9},{%0,%1,%2,%3};"
        : "+f"(c[0]), "+f"(c[1]), "+f"(c[2]), "+f"(c[3])
        : "r"(a0), "r"(a1), "r"(a2), "r"(a3), "r"(b0), "r"(b1));
}

template<int EPI>
__global__ __launch_bounds__(256, 2)
void gemm_tc(const float* __restrict__ A, const float* __restrict__ W,
             const float* __restrict__ bias, const float* __restrict__ res,
             float* __restrict__ out, int M, int N, int K) {
    extern __shared__ uint32_t smem_u[];
    uint32_t* As = smem_u;                        // NSTAGE * AW_STAGE
    uint32_t* Bs = smem_u + NSTAGE * AW_STAGE;    // NSTAGE * BW_STAGE

    int tid  = threadIdx.x;
    int lane = tid & 31, warp = tid >> 5;
    int grp  = lane >> 2, tig = lane & 3;
    int sub  = lane >> 3, tr8 = lane & 7;
    int m0 = blockIdx.y * 256, n0 = blockIdx.x * 64;
    int wm = (warp & 3) * 64;                 // warp M base (4 warps over M)
    int wn = (warp >> 2) * 32;                // warp N base (2 warps over N)
    int ldRow = tid >> 2;                     // 0..63
    int ldCol = (tid & 3) << 2;               // 0,4,8,12 (words)

    uint32_t sA = (uint32_t)__cvta_generic_to_shared(As);
    uint32_t sB = (uint32_t)__cvta_generic_to_shared(Bs);

    int rowAw[4], rowBw[2];
#pragma unroll
    for (int i = 0; i < 4; i++)
        rowAw[i] = (wm + i * 16 + (sub & 1) * 8 + tr8) * 20 + (sub >> 1) * 4;
#pragma unroll
    for (int jp = 0; jp < 2; jp++)
        rowBw[jp] = (wn + jp * 16 + (sub >> 1) * 8 + tr8) * 20 + (sub & 1) * 4;

    float acc[4][4][4] = {};
    const int niter = K >> 4;

#define ISSUE(it) do {                                                        \
        int s_ = (it) % NSTAGE; int k0_ = (it) << 4;                          \
        _Pragma("unroll")                                                     \
        for (int r = 0; r < 256; r += 64)                                     \
            cp16(sA + 4u*(s_*AW_STAGE + (ldRow + r)*20 + ldCol),              \
                 A + (size_t)(m0 + ldRow + r) * K + k0_ + ldCol);             \
        cp16(sB + 4u*(s_*BW_STAGE + ldRow*20 + ldCol),                        \
             W + (size_t)(n0 + ldRow) * K + k0_ + ldCol);                     \
    } while (0)

    ISSUE(0); asm volatile("cp.async.commit_group;");
    if (niter > 1) { ISSUE(1); }
    asm volatile("cp.async.commit_group;");

    for (int it = 0; it < niter; it++) {
        asm volatile("cp.async.wait_group 1;");
        __syncthreads();
        if (it + 2 < niter) { ISSUE(it + 2); }
        asm volatile("cp.async.commit_group;");

        uint32_t baseA = sA + 4u * ((it % NSTAGE) * AW_STAGE);
        uint32_t baseB = sB + 4u * ((it % NSTAGE) * BW_STAGE);
#pragma unroll
        for (int ks = 0; ks < 2; ks++) {
            int kb = ks * 8;
            uint32_t a[4][4], b[2][4];
#pragma unroll
            for (int i = 0; i < 4; i++)
                ldsm4(a[i], baseA + 4u * (rowAw[i] + kb));
            ldsm4(b[0], baseB + 4u * (rowBw[0] + kb));
            ldsm4(b[1], baseB + 4u * (rowBw[1] + kb));
#pragma unroll
            for (int i = 0; i < 4; i++)
#pragma unroll
                for (int j = 0; j < 4; j++)
                    mma_tf32(acc[i][j], a[i][0], a[i][1], a[i][2], a[i][3],
                             b[j >> 1][(j & 1) * 2], b[j >> 1][(j & 1) * 2 + 1]);
        }
    }
#undef ISSUE

#pragma unroll
    for (int i = 0; i < 4; i++) {
#pragma unroll
        for (int h = 0; h < 2; h++) {
            int m = m0 + wm + i * 16 + grp + h * 8;
            int dst = (EPI == EPI_PROJ) ? win_to_tok(m) : m;
#pragma unroll
            for (int j = 0; j < 4; j++) {
                int n = n0 + wn + j * 8 + 2 * tig;
                float v0 = acc[i][j][h * 2 + 0] + bias[n];
                float v1 = acc[i][j][h * 2 + 1] + bias[n + 1];
                size_t oi = (size_t)dst * N + n;
                if (EPI == EPI_GELU) {
                    v0 = 0.5f * v0 * (1.f + erff(v0 * 0.70710678118654752f));
                    v1 = 0.5f * v1 * (1.f + erff(v1 * 0.70710678118654752f));
                } else if (EPI == EPI_PROJ || EPI == EPI_RES) {
                    float2 rv = *(const float2*)(res + oi);
                    v0 += rv.x; v1 += rv.y;
                }
                float2 o = { v0, v1 };
                *(float2*)(out + oi) = o;
            }
        }
    }
}

// ---------------- windowed attention (LDS-optimized scalar) ---------------
// one block per (window, head), 128 threads = 4 warps. fp32 throughout.
__global__ __launch_bounds__(128)
void attn_kernel(const float* __restrict__ qkv,
                 const float* __restrict__ biasT,    // [NHEAD][64*64]
                 const float* __restrict__ mask,     // [768][64*64]
                 float* __restrict__ out) {
    __shared__ float q[NTOK][HDIM];       // broadcast-read only
    __shared__ float k[NTOK][HDIM + 1];   // lane-strided read (pad 33)
    __shared__ float v[NTOK][HDIM + 1];
    __shared__ float S[NTOK][NTOK];       // row 256B -> float4-aligned

    int wg   = blockIdx.x;
    int head = blockIdx.y;
    int tid  = threadIdx.x;
    int lane = tid & 31, warp = tid >> 5;

    const float* base = qkv + (size_t)wg * NTOK * C3 + head * HDIM;
    for (int idx = tid; idx < NTOK * HDIM; idx += 128) {
        int n = idx >> 5, d = idx & 31;
        const float* row = base + (size_t)n * C3 + d;
        q[n][d] = row[0];
        k[n][d] = row[CC];
        v[n][d] = row[2 * CC];
    }
    __syncthreads();

    // ---- QK^T: thread owns column mm; K row in registers; Q via bcast f4
    {
        int mm = tid & 63;
        int nb = tid >> 6;                 // 0 or 1 -> even/odd rows
        float kreg[32];
#pragma unroll
        for (int d = 0; d < 32; d++) kreg[d] = k[mm][d];
        const float* bT   = biasT + head * (NTOK * NTOK);
        const float* mrow = mask + (size_t)(wg % NWIN) * (NTOK * NTOK);
#pragma unroll 4
        for (int t = 0; t < 32; t++) {
            int n = nb + 2 * t;
            float acc = 0.f;
#pragma unroll
            for (int d4 = 0; d4 < 8; d4++) {
                float4 qv = *(const float4*)&q[n][d4 * 4];
                acc = fmaf(qv.x, kreg[d4 * 4 + 0], acc);
                acc = fmaf(qv.y, kreg[d4 * 4 + 1], acc);
                acc = fmaf(qv.z, kreg[d4 * 4 + 2], acc);
                acc = fmaf(qv.w, kreg[d4 * 4 + 3], acc);
            }
            int e = n * 64 + mm;
            S[n][mm] = acc * SCALE + bT[e] + mrow[e];
        }
    }
    __syncthreads();

    // ---- softmax: warp w -> rows 16w..16w+15; lane covers cols l, l+32
    for (int r = 0; r < 16; r++) {
        int row = warp * 16 + r;
        float v0 = S[row][lane], v1 = S[row][lane + 32];
        float mx = fmaxf(v0, v1);
#pragma unroll
        for (int o = 16; o; o >>= 1) mx = fmaxf(mx, __shfl_xor_sync(~0u, mx, o));
        float e0 = expf(v0 - mx), e1 = expf(v1 - mx);
        float s = e0 + e1;
#pragma unroll
        for (int o = 16; o; o >>= 1) s += __shfl_xor_sync(~0u, s, o);
        float inv = 1.f / s;
        S[row][lane] = e0 * inv;
        S[row][lane + 32] = e1 * inv;
    }
    __syncthreads();

    // ---- P.V: lane owns dim d; S via bcast f4; V conflict-free by lane
    {
        int d = tid & 31, nb = tid >> 5;   // nb in 0..3
        float acc[16];
#pragma unroll
        for (int t = 0; t < 16; t++) acc[t] = 0.f;
        for (int m4 = 0; m4 < 16; m4++) {
            float vv0 = v[m4 * 4 + 0][d], vv1 = v[m4 * 4 + 1][d];
            float vv2 = v[m4 * 4 + 2][d], vv3 = v[m4 * 4 + 3][d];
#pragma unroll
            for (int t = 0; t < 16; t++) {
                float4 s4 = *(const float4*)&S[nb + 4 * t][m4 * 4];
                acc[t] = fmaf(s4.x, vv0, acc[t]);
                acc[t] = fmaf(s4.y, vv1, acc[t]);
                acc[t] = fmaf(s4.z, vv2, acc[t]);
                acc[t] = fmaf(s4.w, vv3, acc[t]);
            }
        }
        float* ob = out + (size_t)wg * NTOK * CC + head * HDIM + d;
#pragma unroll
        for (int t = 0; t < 16; t++)
            ob[(size_t)(nb + 4 * t) * CC] = acc[t];
    }
}

// ---------------- launch ---------------------------------------------------
extern "C" void kernel_launch(void* const* d_in, const int* in_sizes, int n_in,
                              void* d_out, int out_size) {
    const float* x        = (const float*)d_in[0];
    const float* qkv_w    = (const float*)d_in[1];
    const float* qkv_b    = (const float*)d_in[2];
    const float* rpb      = (const float*)d_in[3];
    const float* proj_w   = (const float*)d_in[4];
    const float* proj_b   = (const float*)d_in[5];
    const float* g1       = (const float*)d_in[6];
    const float* b1       = (const float*)d_in[7];
    const float* g2       = (const float*)d_in[8];
    const float* b2       = (const float*)d_in[9];
    const float* fc1_w    = (const float*)d_in[10];
    const float* fc1_b    = (const float*)d_in[11];
    const float* fc2_w    = (const float*)d_in[12];
    const float* fc2_b    = (const float*)d_in[13];
    const int*   rel_idx  = (const int*)  d_in[14];
    const float* amask    = (const float*)d_in[15];
    float* out = (float*)d_out;

    float *bufA, *bufB, *biasT;
    cudaGetSymbolAddress((void**)&bufA, g_bufA);
    cudaGetSymbolAddress((void**)&bufB, g_bufB);
    cudaGetSymbolAddress((void**)&biasT, g_biasT);

    float* win  = bufA;
    float* qkvb = bufB;
    float* att  = bufA;                        // win dead
    float* x1   = bufB;                        // qkv dead
    float* h2   = bufB + (size_t)MTOK * CC;
    float* mlpc = bufA;                        // att dead

    cudaFuncSetAttribute(gemm_tc<EPI_BIAS>, cudaFuncAttributeMaxDynamicSharedMemorySize, SMEM_DYN);
    cudaFuncSetAttribute(gemm_tc<EPI_PROJ>, cudaFuncAttributeMaxDynamicSharedMemorySize, SMEM_DYN);
    cudaFuncSetAttribute(gemm_tc<EPI_GELU>, cudaFuncAttributeMaxDynamicSharedMemorySize, SMEM_DYN);
    cudaFuncSetAttribute(gemm_tc<EPI_RES>,  cudaFuncAttributeMaxDynamicSharedMemorySize, SMEM_DYN);

    const int LN_BLOCKS = MTOK / 8;

    // 0) pre-gather relative-position bias (tiny)
    bias_gather_kernel<<<(NHEAD * NTOK * NTOK + 255) / 256, 256>>>(rpb, rel_idx, biasT);

    // 1) LN1 + shift + window partition (gather)
    ln_kernel<true><<<LN_BLOCKS, 256>>>(x, g1, b1, win);

    // 2) QKV GEMM  [M,192] x [576,192]^T -> [M,576]
    gemm_tc<EPI_BIAS><<<dim3(C3 / 64, MTOK / 256), 256, SMEM_DYN>>>(
        win, qkv_w, qkv_b, nullptr, qkvb, MTOK, C3, CC);

    // 3) attention per (window, head)
    attn_kernel<<<dim3(BB * NWIN, NHEAD), 128>>>(qkvb, biasT, amask, att);

    // 4) proj GEMM + window-reverse/unshift scatter + residual -> x1
    gemm_tc<EPI_PROJ><<<dim3(CC / 64, MTOK / 256), 256, SMEM_DYN>>>(
        att, proj_w, proj_b, x, x1, MTOK, CC, CC);

    // 5) LN2
    ln_kernel<false><<<LN_BLOCKS, 256>>>(x1, g2, b2, h2);

    // 6/7) MLP in 4 row-chunks (scratch = MTOK*CC floats exactly)
    for (int c = 0; c < 4; c++) {
        size_t roff = (size_t)c * MCHUNK;
        gemm_tc<EPI_GELU><<<dim3(MLPH / 64, MCHUNK / 256), 256, SMEM_DYN>>>(
            h2 + roff * CC, fc1_w, fc1_b, nullptr, mlpc, MCHUNK, MLPH, CC);
        gemm_tc<EPI_RES><<<dim3(CC / 64, MCHUNK / 256), 256, SMEM_DYN>>>(
            mlpc, fc2_w, fc2_b, x1 + roff * CC, out + roff * CC,
            MCHUNK, CC, MLPH);
    }

    (void)in_sizes; (void)n_in; (void)out_size;
}

// round 9
// speedup vs baseline: 3.2899x; 1.2671x over previous
#include <cuda_runtime.h>
#include <cuda_fp16.h>
#include <math.h>
#include <stdint.h>

// ---------------- problem constants ----------------
#define BB     8
#define HH     128
#define WW     384
#define CC     192
#define NHEAD  6
#define WSZ    8
#define SSZ    4
#define HDIM   32
#define NWIN   768
#define NTOK   64
#define HWSZ   (HH*WW)             // 49152
#define MTOK   (BB*HWSZ)           // 393216
#define C3     (3*CC)              // 576
#define MLPH   (4*CC)              // 768
#define SCALE  0.1767766952966369f
#define MCHUNK (MTOK/4)            // 98304

// ---------------- scratch (aliased; keep <2GB total for host link) --------
__device__ float g_bufA[(size_t)MTOK * CC];    // win/att/mlp (as half) reuse
__device__ float g_bufB[(size_t)MTOK * C3];    // qkv(f32) -> (x1 | h2)
__device__ float g_biasT[NHEAD * NTOK * NTOK]; // rpb[rel_idx] pre-gathered
__device__ __half g_wh[C3*CC + CC*CC + MLPH*CC + CC*MLPH]; // fp16 weights

#define WOFF_QKV  0
#define WOFF_PROJ (C3*CC)
#define WOFF_FC1  (C3*CC + CC*CC)
#define WOFF_FC2  (C3*CC + CC*CC + MLPH*CC)

__device__ __forceinline__ int win_to_tok(int m) {
    int b  = m / HWSZ;
    int r  = m - b * HWSZ;
    int w  = r >> 6;
    int nt = r & 63;
    int wrow = w / 48;
    int wcol = w - wrow * 48;
    int sh = (wrow << 3) + (nt >> 3);
    int sw = (wcol << 3) + (nt & 7);
    int fh = (sh + SSZ) & (HH - 1);
    int fw = sw + SSZ; if (fw >= WW) fw -= WW;
    return b * HWSZ + fh * WW + fw;
}

// ---------------- tiny prep kernels ---------------------------------------
__global__ void w2h_kernel(const float* __restrict__ s, __half* __restrict__ d, int n) {
    int i = blockIdx.x * blockDim.x + threadIdx.x;
    if (i < n) d[i] = __float2half_rn(s[i]);
}
__global__ void bias_gather_kernel(const float* __restrict__ rpb,
                                   const int* __restrict__ rel_idx,
                                   float* __restrict__ biasT) {
    int i = blockIdx.x * blockDim.x + threadIdx.x;
    if (i >= NHEAD * NTOK * NTOK) return;
    int h = i / (NTOK * NTOK), e = i % (NTOK * NTOK);
    biasT[i] = rpb[rel_idx[e] * NHEAD + h];
}

// ---------------- LayerNorm (one warp per token) -> fp16 out --------------
template<bool GATHER>
__global__ void ln_kernel(const float* __restrict__ x,
                          const float* __restrict__ gamma,
                          const float* __restrict__ beta,
                          __half* __restrict__ out) {
    int warp = blockIdx.x * (blockDim.x >> 5) + (threadIdx.x >> 5);
    if (warp >= MTOK) return;
    int lane = threadIdx.x & 31;
    int src = GATHER ? win_to_tok(warp) : warp;
    const float* xr = x + (size_t)src * CC;
    float v[6], s = 0.f, ss = 0.f;
#pragma unroll
    for (int i = 0; i < 6; i++) {
        float t = xr[lane + i * 32];
        v[i] = t; s += t; ss += t * t;
    }
#pragma unroll
    for (int o = 16; o; o >>= 1) {
        s  += __shfl_xor_sync(0xffffffffu, s,  o);
        ss += __shfl_xor_sync(0xffffffffu, ss, o);
    }
    float mean = s * (1.f / CC);
    float var  = ss * (1.f / CC) - mean * mean;
    float rstd = rsqrtf(var + 1e-5f);
    __half* orow = out + (size_t)warp * CC;
#pragma unroll
    for (int i = 0; i < 6; i++) {
        int c = lane + i * 32;
        orow[c] = __float2half_rn((v[i] - mean) * rstd * gamma[c] + beta[c]);
    }
}

// ---------------- FP16 mma GEMM, BM=256 BN=64 BK=32, 3-stage --------------
// out[m,n] = sum_k A[m,k]*W[n,k] (+epilogue). A [M,K] fp16, W [N,K] fp16.
// 256 threads = 8 warps (4Mx2N), warp tile 64x32 = 4x4 m16n8k16 MMAs x 2
// k-steps. Row stride 40 halves (80B): LDSM octet rows hit banks at spacing
// 4 -> conflict-free. 3-stage cp.async ring, one __syncthreads per iter.
#define EPI_BIAS 0
#define EPI_PROJ 1
#define EPI_GELU 2
#define EPI_RES  3

#define NSTAGE   3
#define AH_STAGE (256*40)   // halves per A stage
#define BH_STAGE (64*40)    // halves per B stage
#define SMEM_DYN (NSTAGE * (AH_STAGE + BH_STAGE) * 2)

__device__ __forceinline__ void cp16(uint32_t s, const void* g) {
    asm volatile("cp.async.cg.shared.global [%0], [%1], 16;" :: "r"(s), "l"(g));
}
__device__ __forceinline__ void ldsm4(uint32_t* r, uint32_t addr) {
    asm volatile("ldmatrix.sync.aligned.m8n8.x4.shared.b16 {%0,%1,%2,%3}, [%4];"
        : "=r"(r[0]), "=r"(r[1]), "=r"(r[2]), "=r"(r[3]) : "r"(addr));
}
__device__ __forceinline__ void mma_f16(float c[4],
        uint32_t a0, uint32_t a1, uint32_t a2, uint32_t a3,
        uint32_t b0, uint32_t b1) {
    asm volatile(
        "mma.sync.aligned.m16n8k16.row.col.f32.f16.f16.f32 "
        "{%0,%1,%2,%3},{%4,%5,%6,%7},{%8,%9},{%0,%1,%2,%3};"
        : "+f"(c[0]), "+f"(c[1]), "+f"(c[2]), "+f"(c[3])
        : "r"(a0), "r"(a1), "r"(a2), "r"(a3), "r"(b0), "r"(b1));
}

template<int EPI>
__global__ __launch_bounds__(256, 2)
void gemm_tc(const __half* __restrict__ A, const __half* __restrict__ W,
             const float* __restrict__ bias, const float* __restrict__ res,
             void* __restrict__ outv, int M, int N, int K) {
    extern __shared__ __half smem_h[];
    __half* As = smem_h;                        // NSTAGE * AH_STAGE
    __half* Bs = smem_h + NSTAGE * AH_STAGE;    // NSTAGE * BH_STAGE

    int tid  = threadIdx.x;
    int lane = tid & 31, warp = tid >> 5;
    int grp  = lane >> 2, tig = lane & 3;
    int sub  = lane >> 3, tr8 = lane & 7;
    int m0 = blockIdx.y * 256, n0 = blockIdx.x * 64;
    int wm = (warp & 3) * 64;                 // warp M base (4 warps over M)
    int wn = (warp >> 2) * 32;                // warp N base (2 warps over N)
    int ldRow = tid >> 2;                     // 0..63
    int ldColh = (tid & 3) << 3;              // 0,8,16,24 (halves)

    uint32_t sA = (uint32_t)__cvta_generic_to_shared(As);
    uint32_t sB = (uint32_t)__cvta_generic_to_shared(Bs);

    // LDSM half-offsets within a stage: octet rows + k-half selector
    int rowAh[4], rowBh[2];
#pragma unroll
    for (int i = 0; i < 4; i++)
        rowAh[i] = (wm + i * 16 + (sub & 1) * 8 + tr8) * 40 + (sub >> 1) * 8;
#pragma unroll
    for (int g = 0; g < 2; g++)
        rowBh[g] = (wn + g * 16 + (sub & 1) * 8 + tr8) * 40 + (sub >> 1) * 8;

    float acc[4][4][4] = {};
    const int niter = K >> 5;

#define ISSUE(it) do {                                                        \
        int s_ = (it) % NSTAGE; int k0_ = (it) << 5;                          \
        _Pragma("unroll")                                                     \
        for (int r = 0; r < 256; r += 64)                                     \
            cp16(sA + 2u*(s_*AH_STAGE + (ldRow + r)*40 + ldColh),             \
                 A + (size_t)(m0 + ldRow + r) * K + k0_ + ldColh);            \
        cp16(sB + 2u*(s_*BH_STAGE + ldRow*40 + ldColh),                       \
             W + (size_t)(n0 + ldRow) * K + k0_ + ldColh);                    \
    } while (0)

    ISSUE(0); asm volatile("cp.async.commit_group;");
    if (niter > 1) { ISSUE(1); }
    asm volatile("cp.async.commit_group;");

    for (int it = 0; it < niter; it++) {
        asm volatile("cp.async.wait_group 1;");
        __syncthreads();
        if (it + 2 < niter) { ISSUE(it + 2); }
        asm volatile("cp.async.commit_group;");

        uint32_t baseA = sA + 2u * ((it % NSTAGE) * AH_STAGE);
        uint32_t baseB = sB + 2u * ((it % NSTAGE) * BH_STAGE);
#pragma unroll
        for (int ks = 0; ks < 2; ks++) {
            int kb = ks * 16;                 // halves
            uint32_t a[4][4], b[2][4];
#pragma unroll
            for (int i = 0; i < 4; i++)
                ldsm4(a[i], baseA + 2u * (rowAh[i] + kb));
            ldsm4(b[0], baseB + 2u * (rowBh[0] + kb));
            ldsm4(b[1], baseB + 2u * (rowBh[1] + kb));
#pragma unroll
            for (int i = 0; i < 4; i++)
#pragma unroll
                for (int j = 0; j < 4; j++) {
                    int g = j >> 1, jn = j & 1;
                    mma_f16(acc[i][j], a[i][0], a[i][1], a[i][2], a[i][3],
                            b[g][jn], b[g][2 + jn]);
                }
        }
    }
#undef ISSUE

    // epilogue: c0/c1 -> row grp, cols 2tig/2tig+1; c2/c3 -> row grp+8
#pragma unroll
    for (int i = 0; i < 4; i++) {
#pragma unroll
        for (int h = 0; h < 2; h++) {
            int m = m0 + wm + i * 16 + grp + h * 8;
            int dst = (EPI == EPI_PROJ) ? win_to_tok(m) : m;
#pragma unroll
            for (int j = 0; j < 4; j++) {
                int n = n0 + wn + j * 8 + 2 * tig;
                float v0 = acc[i][j][h * 2 + 0] + bias[n];
                float v1 = acc[i][j][h * 2 + 1] + bias[n + 1];
                size_t oi = (size_t)dst * N + n;
                if (EPI == EPI_GELU) {
                    v0 = 0.5f * v0 * (1.f + erff(v0 * 0.70710678118654752f));
                    v1 = 0.5f * v1 * (1.f + erff(v1 * 0.70710678118654752f));
                    __half2 hv = __floats2half2_rn(v0, v1);
                    *(__half2*)((__half*)outv + oi) = hv;
                } else {
                    if (EPI == EPI_PROJ || EPI == EPI_RES) {
                        float2 rv = *(const float2*)(res + oi);
                        v0 += rv.x; v1 += rv.y;
                    }
                    float2 o = { v0, v1 };
                    *(float2*)((float*)outv + oi) = o;
                }
            }
        }
    }
}

// ---------------- windowed attention (LDS-optimized scalar) ---------------
// one block per (window, head), 128 threads. fp32 math; fp16 output.
__global__ __launch_bounds__(128)
void attn_kernel(const float* __restrict__ qkv,
                 const float* __restrict__ biasT,    // [NHEAD][64*64]
                 const float* __restrict__ mask,     // [768][64*64]
                 __half* __restrict__ out) {         // [M,192] window layout
    __shared__ float q[NTOK][HDIM];       // broadcast-read only
    __shared__ float k[NTOK][HDIM + 1];
    __shared__ float v[NTOK][HDIM + 1];
    __shared__ float S[NTOK][NTOK];

    int wg   = blockIdx.x;
    int head = blockIdx.y;
    int tid  = threadIdx.x;
    int lane = tid & 31, warp = tid >> 5;

    const float* base = qkv + (size_t)wg * NTOK * C3 + head * HDIM;
    for (int idx = tid; idx < NTOK * HDIM; idx += 128) {
        int n = idx >> 5, d = idx & 31;
        const float* row = base + (size_t)n * C3 + d;
        q[n][d] = row[0];
        k[n][d] = row[CC];
        v[n][d] = row[2 * CC];
    }
    __syncthreads();

    {
        int mm = tid & 63;
        int nb = tid >> 6;
        float kreg[32];
#pragma unroll
        for (int d = 0; d < 32; d++) kreg[d] = k[mm][d];
        const float* bT   = biasT + head * (NTOK * NTOK);
        const float* mrow = mask + (size_t)(wg % NWIN) * (NTOK * NTOK);
#pragma unroll 4
        for (int t = 0; t < 32; t++) {
            int n = nb + 2 * t;
            float acc = 0.f;
#pragma unroll
            for (int d4 = 0; d4 < 8; d4++) {
                float4 qv = *(const float4*)&q[n][d4 * 4];
                acc = fmaf(qv.x, kreg[d4 * 4 + 0], acc);
                acc = fmaf(qv.y, kreg[d4 * 4 + 1], acc);
                acc = fmaf(qv.z, kreg[d4 * 4 + 2], acc);
                acc = fmaf(qv.w, kreg[d4 * 4 + 3], acc);
            }
            int e = n * 64 + mm;
            S[n][mm] = acc * SCALE + bT[e] + mrow[e];
        }
    }
    __syncthreads();

    for (int r = 0; r < 16; r++) {
        int row = warp * 16 + r;
        float v0 = S[row][lane], v1 = S[row][lane + 32];
        float mx = fmaxf(v0, v1);
#pragma unroll
        for (int o = 16; o; o >>= 1) mx = fmaxf(mx, __shfl_xor_sync(~0u, mx, o));
        float e0 = expf(v0 - mx), e1 = expf(v1 - mx);
        float s = e0 + e1;
#pragma unroll
        for (int o = 16; o; o >>= 1) s += __shfl_xor_sync(~0u, s, o);
        float inv = 1.f / s;
        S[row][lane] = e0 * inv;
        S[row][lane + 32] = e1 * inv;
    }
    __syncthreads();

    {
        int d = tid & 31, nb = tid >> 5;
        float acc[16];
#pragma unroll
        for (int t = 0; t < 16; t++) acc[t] = 0.f;
        for (int m4 = 0; m4 < 16; m4++) {
            float vv0 = v[m4 * 4 + 0][d], vv1 = v[m4 * 4 + 1][d];
            float vv2 = v[m4 * 4 + 2][d], vv3 = v[m4 * 4 + 3][d];
#pragma unroll
            for (int t = 0; t < 16; t++) {
                float4 s4 = *(const float4*)&S[nb + 4 * t][m4 * 4];
                acc[t] = fmaf(s4.x, vv0, acc[t]);
                acc[t] = fmaf(s4.y, vv1, acc[t]);
                acc[t] = fmaf(s4.z, vv2, acc[t]);
                acc[t] = fmaf(s4.w, vv3, acc[t]);
            }
        }
        __half* ob = out + (size_t)wg * NTOK * CC + head * HDIM + d;
#pragma unroll
        for (int t = 0; t < 16; t++)
            ob[(size_t)(nb + 4 * t) * CC] = __float2half_rn(acc[t]);
    }
}

// ---------------- launch ---------------------------------------------------
extern "C" void kernel_launch(void* const* d_in, const int* in_sizes, int n_in,
                              void* d_out, int out_size) {
    const float* x        = (const float*)d_in[0];
    const float* qkv_w    = (const float*)d_in[1];
    const float* qkv_b    = (const float*)d_in[2];
    const float* rpb      = (const float*)d_in[3];
    const float* proj_w   = (const float*)d_in[4];
    const float* proj_b   = (const float*)d_in[5];
    const float* g1       = (const float*)d_in[6];
    const float* b1       = (const float*)d_in[7];
    const float* g2       = (const float*)d_in[8];
    const float* b2       = (const float*)d_in[9];
    const float* fc1_w    = (const float*)d_in[10];
    const float* fc1_b    = (const float*)d_in[11];
    const float* fc2_w    = (const float*)d_in[12];
    const float* fc2_b    = (const float*)d_in[13];
    const int*   rel_idx  = (const int*)  d_in[14];
    const float* amask    = (const float*)d_in[15];
    float* out = (float*)d_out;

    float *bufA, *bufB, *biasT;
    __half* wh;
    cudaGetSymbolAddress((void**)&bufA, g_bufA);
    cudaGetSymbolAddress((void**)&bufB, g_bufB);
    cudaGetSymbolAddress((void**)&biasT, g_biasT);
    cudaGetSymbolAddress((void**)&wh, g_wh);

    __half* win  = (__half*)bufA;
    float*  qkvb = bufB;
    __half* att  = (__half*)bufA;                  // win dead
    float*  x1   = bufB;                           // qkv dead
    __half* h2   = (__half*)(bufB + (size_t)MTOK * CC);
    __half* mlpc = (__half*)bufA;                  // att dead

    cudaFuncSetAttribute(gemm_tc<EPI_BIAS>, cudaFuncAttributeMaxDynamicSharedMemorySize, SMEM_DYN);
    cudaFuncSetAttribute(gemm_tc<EPI_PROJ>, cudaFuncAttributeMaxDynamicSharedMemorySize, SMEM_DYN);
    cudaFuncSetAttribute(gemm_tc<EPI_GELU>, cudaFuncAttributeMaxDynamicSharedMemorySize, SMEM_DYN);
    cudaFuncSetAttribute(gemm_tc<EPI_RES>,  cudaFuncAttributeMaxDynamicSharedMemorySize, SMEM_DYN);

    const int LN_BLOCKS = MTOK / 8;

    // 0) prep: fp16 weights + bias pre-gather (all tiny)
    w2h_kernel<<<(C3*CC   + 255)/256, 256>>>(qkv_w,  wh + WOFF_QKV,  C3*CC);
    w2h_kernel<<<(CC*CC   + 255)/256, 256>>>(proj_w, wh + WOFF_PROJ, CC*CC);
    w2h_kernel<<<(MLPH*CC + 255)/256, 256>>>(fc1_w,  wh + WOFF_FC1,  MLPH*CC);
    w2h_kernel<<<(CC*MLPH + 255)/256, 256>>>(fc2_w,  wh + WOFF_FC2,  CC*MLPH);
    bias_gather_kernel<<<(NHEAD*NTOK*NTOK + 255)/256, 256>>>(rpb, rel_idx, biasT);

    // 1) LN1 + shift + window partition (gather) -> fp16
    ln_kernel<true><<<LN_BLOCKS, 256>>>(x, g1, b1, win);

    // 2) QKV GEMM  [M,192]h x [576,192]h^T -> [M,576] f32
    gemm_tc<EPI_BIAS><<<dim3(C3 / 64, MTOK / 256), 256, SMEM_DYN>>>(
        win, wh + WOFF_QKV, qkv_b, nullptr, qkvb, MTOK, C3, CC);

    // 3) attention per (window, head) -> fp16
    attn_kernel<<<dim3(BB * NWIN, NHEAD), 128>>>(qkvb, biasT, amask, att);

    // 4) proj GEMM + window-reverse/unshift scatter + residual -> x1 f32
    gemm_tc<EPI_PROJ><<<dim3(CC / 64, MTOK / 256), 256, SMEM_DYN>>>(
        att, wh + WOFF_PROJ, proj_b, x, x1, MTOK, CC, CC);

    // 5) LN2 -> fp16
    ln_kernel<false><<<LN_BLOCKS, 256>>>(x1, g2, b2, h2);

    // 6/7) MLP in 4 row-chunks
    for (int c = 0; c < 4; c++) {
        size_t roff = (size_t)c * MCHUNK;
        gemm_tc<EPI_GELU><<<dim3(MLPH / 64, MCHUNK / 256), 256, SMEM_DYN>>>(
            h2 + roff * CC, wh + WOFF_FC1, fc1_b, nullptr, mlpc,
            MCHUNK, MLPH, CC);
        gemm_tc<EPI_RES><<<dim3(CC / 64, MCHUNK / 256), 256, SMEM_DYN>>>(
            mlpc, wh + WOFF_FC2, fc2_b, x1 + roff * CC, out + roff * CC,
            MCHUNK, CC, MLPH);
    }

    (void)in_sizes; (void)n_in; (void)out_size;
}

// round 11
// speedup vs baseline: 3.7464x; 1.1388x over previous
#include <cuda_runtime.h>
#include <cuda_fp16.h>
#include <math.h>
#include <stdint.h>

// ---------------- problem constants ----------------
#define BB     8
#define HH     128
#define WW     384
#define CC     192
#define NHEAD  6
#define WSZ    8
#define SSZ    4
#define HDIM   32
#define NWIN   768
#define NTOK   64
#define HWSZ   (HH*WW)             // 49152
#define MTOK   (BB*HWSZ)           // 393216
#define C3     (3*CC)              // 576
#define MLPH   (4*CC)              // 768
#define SCALE  0.1767766952966369f
#define MCHUNK (MTOK/4)            // 98304

// ---------------- scratch (aliased; keep <2GB total for host link) --------
__device__ float g_bufA[(size_t)MTOK * CC];    // win/att/mlp (as half) reuse
__device__ float g_bufB[(size_t)MTOK * C3];    // qkv(h) -> (x1 | h2)
__device__ float g_biasT[NHEAD * NTOK * NTOK]; // rpb[rel_idx] pre-gathered
__device__ __half g_wh[C3*CC + CC*CC + MLPH*CC + CC*MLPH]; // fp16 weights

#define WOFF_QKV  0
#define WOFF_PROJ (C3*CC)
#define WOFF_FC1  (C3*CC + CC*CC)
#define WOFF_FC2  (C3*CC + CC*CC + MLPH*CC)

__device__ __forceinline__ int win_to_tok(int m) {
    int b  = m / HWSZ;
    int r  = m - b * HWSZ;
    int w  = r >> 6;
    int nt = r & 63;
    int wrow = w / 48;
    int wcol = w - wrow * 48;
    int sh = (wrow << 3) + (nt >> 3);
    int sw = (wcol << 3) + (nt & 7);
    int fh = (sh + SSZ) & (HH - 1);
    int fw = sw + SSZ; if (fw >= WW) fw -= WW;
    return b * HWSZ + fh * WW + fw;
}

// ---------------- tiny prep kernels ---------------------------------------
__global__ void w2h_kernel(const float* __restrict__ s, __half* __restrict__ d, int n) {
    int i = blockIdx.x * blockDim.x + threadIdx.x;
    if (i < n) d[i] = __float2half_rn(s[i]);
}
__global__ void bias_gather_kernel(const float* __restrict__ rpb,
                                   const int* __restrict__ rel_idx,
                                   float* __restrict__ biasT) {
    int i = blockIdx.x * blockDim.x + threadIdx.x;
    if (i >= NHEAD * NTOK * NTOK) return;
    int h = i / (NTOK * NTOK), e = i % (NTOK * NTOK);
    biasT[i] = rpb[rel_idx[e] * NHEAD + h];
}

// ---------------- LayerNorm (one warp per token) -> fp16 out --------------
template<bool GATHER>
__global__ void ln_kernel(const float* __restrict__ x,
                          const float* __restrict__ gamma,
                          const float* __restrict__ beta,
                          __half* __restrict__ out) {
    int warp = blockIdx.x * (blockDim.x >> 5) + (threadIdx.x >> 5);
    if (warp >= MTOK) return;
    int lane = threadIdx.x & 31;
    int src = GATHER ? win_to_tok(warp) : warp;
    const float* xr = x + (size_t)src * CC;
    float v[6], s = 0.f, ss = 0.f;
#pragma unroll
    for (int i = 0; i < 6; i++) {
        float t = xr[lane + i * 32];
        v[i] = t; s += t; ss += t * t;
    }
#pragma unroll
    for (int o = 16; o; o >>= 1) {
        s  += __shfl_xor_sync(0xffffffffu, s,  o);
        ss += __shfl_xor_sync(0xffffffffu, ss, o);
    }
    float mean = s * (1.f / CC);
    float var  = ss * (1.f / CC) - mean * mean;
    float rstd = rsqrtf(var + 1e-5f);
    __half* orow = out + (size_t)warp * CC;
#pragma unroll
    for (int i = 0; i < 6; i++) {
        int c = lane + i * 32;
        orow[c] = __float2half_rn((v[i] - mean) * rstd * gamma[c] + beta[c]);
    }
}

// ---------------- shared MMA helpers --------------------------------------
__device__ __forceinline__ void cp16(uint32_t s, const void* g) {
    asm volatile("cp.async.cg.shared.global [%0], [%1], 16;" :: "r"(s), "l"(g));
}
__device__ __forceinline__ void ldsm4(uint32_t* r, uint32_t addr) {
    asm volatile("ldmatrix.sync.aligned.m8n8.x4.shared.b16 {%0,%1,%2,%3}, [%4];"
        : "=r"(r[0]), "=r"(r[1]), "=r"(r[2]), "=r"(r[3]) : "r"(addr));
}
__device__ __forceinline__ void mma_f16(float c[4],
        uint32_t a0, uint32_t a1, uint32_t a2, uint32_t a3,
        uint32_t b0, uint32_t b1) {
    asm volatile(
        "mma.sync.aligned.m16n8k16.row.col.f32.f16.f16.f32 "
        "{%0,%1,%2,%3},{%4,%5,%6,%7},{%8,%9},{%0,%1,%2,%3};"
        : "+f"(c[0]), "+f"(c[1]), "+f"(c[2]), "+f"(c[3])
        : "r"(a0), "r"(a1), "r"(a2), "r"(a3), "r"(b0), "r"(b1));
}

// ---------------- FP16 mma GEMM, BM=256 BN=64 BK=32, 3-stage --------------
#define EPI_QKVH 0   // out = half(acc + bias)
#define EPI_PROJ 1   // f32: scatter + residual
#define EPI_GELU 2   // half: gelu(acc + bias)
#define EPI_RES  3   // f32: residual

#define NSTAGE   3
#define AH_STAGE (256*40)
#define BH_STAGE (64*40)
#define SMEM_DYN (NSTAGE * (AH_STAGE + BH_STAGE) * 2)

template<int EPI>
__global__ __launch_bounds__(256, 2)
void gemm_tc(const __half* __restrict__ A, const __half* __restrict__ W,
             const float* __restrict__ bias, const float* __restrict__ res,
             void* __restrict__ outv, int M, int N, int K) {
    extern __shared__ __half smem_h[];
    __half* As = smem_h;
    __half* Bs = smem_h + NSTAGE * AH_STAGE;

    int tid  = threadIdx.x;
    int lane = tid & 31, warp = tid >> 5;
    int grp  = lane >> 2, tig = lane & 3;
    int sub  = lane >> 3, tr8 = lane & 7;
    int m0 = blockIdx.y * 256, n0 = blockIdx.x * 64;
    int wm = (warp & 3) * 64;
    int wn = (warp >> 2) * 32;
    int ldRow = tid >> 2;
    int ldColh = (tid & 3) << 3;

    uint32_t sA = (uint32_t)__cvta_generic_to_shared(As);
    uint32_t sB = (uint32_t)__cvta_generic_to_shared(Bs);

    int rowAh[4], rowBh[2];
#pragma unroll
    for (int i = 0; i < 4; i++)
        rowAh[i] = (wm + i * 16 + (sub & 1) * 8 + tr8) * 40 + (sub >> 1) * 8;
#pragma unroll
    for (int g = 0; g < 2; g++)
        rowBh[g] = (wn + g * 16 + (sub & 1) * 8 + tr8) * 40 + (sub >> 1) * 8;

    float acc[4][4][4] = {};
    const int niter = K >> 5;

#define ISSUE(it) do {                                                        \
        int s_ = (it) % NSTAGE; int k0_ = (it) << 5;                          \
        _Pragma("unroll")                                                     \
        for (int r = 0; r < 256; r += 64)                                     \
            cp16(sA + 2u*(s_*AH_STAGE + (ldRow + r)*40 + ldColh),             \
                 A + (size_t)(m0 + ldRow + r) * K + k0_ + ldColh);            \
        cp16(sB + 2u*(s_*BH_STAGE + ldRow*40 + ldColh),                       \
             W + (size_t)(n0 + ldRow) * K + k0_ + ldColh);                    \
    } while (0)

    ISSUE(0); asm volatile("cp.async.commit_group;");
    if (niter > 1) { ISSUE(1); }
    asm volatile("cp.async.commit_group;");

    for (int it = 0; it < niter; it++) {
        asm volatile("cp.async.wait_group 1;");
        __syncthreads();
        if (it + 2 < niter) { ISSUE(it + 2); }
        asm volatile("cp.async.commit_group;");

        uint32_t baseA = sA + 2u * ((it % NSTAGE) * AH_STAGE);
        uint32_t baseB = sB + 2u * ((it % NSTAGE) * BH_STAGE);
#pragma unroll
        for (int ks = 0; ks < 2; ks++) {
            int kb = ks * 16;
            uint32_t a[4][4], b[2][4];
#pragma unroll
            for (int i = 0; i < 4; i++)
                ldsm4(a[i], baseA + 2u * (rowAh[i] + kb));
            ldsm4(b[0], baseB + 2u * (rowBh[0] + kb));
            ldsm4(b[1], baseB + 2u * (rowBh[1] + kb));
#pragma unroll
            for (int i = 0; i < 4; i++)
#pragma unroll
                for (int j = 0; j < 4; j++) {
                    int g = j >> 1, jn = j & 1;
                    mma_f16(acc[i][j], a[i][0], a[i][1], a[i][2], a[i][3],
                            b[g][jn], b[g][2 + jn]);
                }
        }
    }
#undef ISSUE

#pragma unroll
    for (int i = 0; i < 4; i++) {
#pragma unroll
        for (int h = 0; h < 2; h++) {
            int m = m0 + wm + i * 16 + grp + h * 8;
            int dst = (EPI == EPI_PROJ) ? win_to_tok(m) : m;
#pragma unroll
            for (int j = 0; j < 4; j++) {
                int n = n0 + wn + j * 8 + 2 * tig;
                float v0 = acc[i][j][h * 2 + 0] + bias[n];
                float v1 = acc[i][j][h * 2 + 1] + bias[n + 1];
                size_t oi = (size_t)dst * N + n;
                if (EPI == EPI_QKVH) {
                    *(__half2*)((__half*)outv + oi) = __floats2half2_rn(v0, v1);
                } else if (EPI == EPI_GELU) {
                    v0 = 0.5f * v0 * (1.f + erff(v0 * 0.70710678118654752f));
                    v1 = 0.5f * v1 * (1.f + erff(v1 * 0.70710678118654752f));
                    *(__half2*)((__half*)outv + oi) = __floats2half2_rn(v0, v1);
                } else {
                    float2 rv = *(const float2*)(res + oi);
                    float2 o = { v0 + rv.x, v1 + rv.y };
                    *(float2*)((float*)outv + oi) = o;
                }
            }
        }
    }
}

// ---------------- windowed attention (fp16 MMA) ---------------------------
// one block per (window, head), 128 threads = 4 warps; warp w owns rows
// 16w..16w+15. QK^T and P.V via m16n8k16; softmax fp32 in smem.
__global__ __launch_bounds__(128)
void attn_kernel(const __half* __restrict__ qkv,
                 const float* __restrict__ biasT,    // [NHEAD][64*64]
                 const float* __restrict__ mask,     // [768][64*64]
                 __half* __restrict__ out) {         // [M,192] half
    __shared__ __half qs[NTOK][40];      // stride 40h: ldsm conflict-free
    __shared__ __half ks_[NTOK][40];
    __shared__ __half vt[HDIM][72];      // V^T; stride 72h (36w) conflict-free
    __shared__ float  S[NTOK][NTOK];
    __shared__ __half Ph[NTOK][72];

    int wg = blockIdx.x, head = blockIdx.y, tid = threadIdx.x;
    int lane = tid & 31, warp = tid >> 5;
    int grp = lane >> 2, tig = lane & 3;
    int sub = lane >> 3, tr8 = lane & 7;

    // load q,k (vector), v transposed (scalar writes)
    const __half* base = qkv + (size_t)wg * NTOK * C3 + head * HDIM;
    for (int t = tid; t < 256; t += 128) {
        int n = t >> 2, c = t & 3;
        const __half* row = base + (size_t)n * C3 + c * 8;
        *(uint4*)&qs[n][c * 8]  = *(const uint4*)(row);
        *(uint4*)&ks_[n][c * 8] = *(const uint4*)(row + CC);
        uint4 vv = *(const uint4*)(row + 2 * CC);
        __half tmp[8]; *(uint4*)tmp = vv;
#pragma unroll
        for (int i = 0; i < 8; i++) vt[c * 8 + i][n] = tmp[i];
    }
    __syncthreads();

    uint32_t sq = (uint32_t)__cvta_generic_to_shared(qs);
    uint32_t sk = (uint32_t)__cvta_generic_to_shared(ks_);
    uint32_t sv = (uint32_t)__cvta_generic_to_shared(vt);
    uint32_t sp = (uint32_t)__cvta_generic_to_shared(Ph);

    int n0 = warp * 16;
    int rowA8 = n0 + (sub & 1) * 8 + tr8;   // A octet row
    int kA = (sub >> 1) * 8;                 // A k-half selector

    // ---- QK^T -> S (+scale +bias +mask)
    float sc[8][4] = {};
#pragma unroll
    for (int ks = 0; ks < 2; ks++) {
        uint32_t a[4];
        ldsm4(a, sq + 2u * (rowA8 * 40 + kA + ks * 16));
#pragma unroll
        for (int g = 0; g < 4; g++) {
            uint32_t b[4];
            int rowB = g * 16 + (sub & 1) * 8 + tr8;
            ldsm4(b, sk + 2u * (rowB * 40 + kA + ks * 16));
#pragma unroll
            for (int jn = 0; jn < 2; jn++)
                mma_f16(sc[g * 2 + jn], a[0], a[1], a[2], a[3], b[jn], b[2 + jn]);
        }
    }
    const float* bT   = biasT + head * (NTOK * NTOK);
    const float* mrow = mask + (size_t)(wg % NWIN) * (NTOK * NTOK);
#pragma unroll
    for (int j = 0; j < 8; j++) {
#pragma unroll
        for (int h = 0; h < 2; h++) {
            int n = n0 + grp + h * 8;
            int m = j * 8 + 2 * tig;
            int e = n * 64 + m;
            float2 bb = *(const float2*)(bT + e);
            float2 mk = *(const float2*)(mrow + e);
            S[n][m]     = sc[j][h * 2 + 0] * SCALE + bb.x + mk.x;
            S[n][m + 1] = sc[j][h * 2 + 1] * SCALE + bb.y + mk.y;
        }
    }
    __syncthreads();

    // ---- softmax: warp w -> rows 16w..16w+15
    for (int r = 0; r < 16; r++) {
        int row = warp * 16 + r;
        float v0 = S[row][lane], v1 = S[row][lane + 32];
        float mx = fmaxf(v0, v1);
#pragma unroll
        for (int o = 16; o; o >>= 1) mx = fmaxf(mx, __shfl_xor_sync(~0u, mx, o));
        float e0 = expf(v0 - mx), e1 = expf(v1 - mx);
        float s = e0 + e1;
#pragma unroll
        for (int o = 16; o; o >>= 1) s += __shfl_xor_sync(~0u, s, o);
        float inv = 1.f / s;
        S[row][lane] = e0 * inv;
        S[row][lane + 32] = e1 * inv;
    }
    __syncthreads();

    // ---- convert S -> Ph (fp16)
    for (int t = tid; t < 2048; t += 128) {
        int n = t >> 5, mp = (t & 31) * 2;
        float2 s2 = *(const float2*)&S[n][mp];
        *(__half2*)&Ph[n][mp] = __floats2half2_rn(s2.x, s2.y);
    }
    __syncthreads();

    // ---- P.V -> out
    float oc[4][4] = {};
#pragma unroll
    for (int ks = 0; ks < 4; ks++) {
        uint32_t a[4];
        ldsm4(a, sp + 2u * (rowA8 * 72 + kA + ks * 16));
#pragma unroll
        for (int g = 0; g < 2; g++) {
            uint32_t b[4];
            int rowB = g * 16 + (sub & 1) * 8 + tr8;
            ldsm4(b, sv + 2u * (rowB * 72 + kA + ks * 16));
#pragma unroll
            for (int jn = 0; jn < 2; jn++)
                mma_f16(oc[g * 2 + jn], a[0], a[1], a[2], a[3], b[jn], b[2 + jn]);
        }
    }
    __half* ob = out + (size_t)wg * NTOK * CC + head * HDIM;
#pragma unroll
    for (int j = 0; j < 4; j++) {
#pragma unroll
        for (int h = 0; h < 2; h++) {
            int n = n0 + grp + h * 8;
            int d = j * 8 + 2 * tig;
            *(__half2*)(ob + (size_t)n * CC + d) =
                __floats2half2_rn(oc[j][h * 2], oc[j][h * 2 + 1]);
        }
    }
}

// ---------------- launch ---------------------------------------------------
extern "C" void kernel_launch(void* const* d_in, const int* in_sizes, int n_in,
                              void* d_out, int out_size) {
    const float* x        = (const float*)d_in[0];
    const float* qkv_w    = (const float*)d_in[1];
    const float* qkv_b    = (const float*)d_in[2];
    const float* rpb      = (const float*)d_in[3];
    const float* proj_w   = (const float*)d_in[4];
    const float* proj_b   = (const float*)d_in[5];
    const float* g1       = (const float*)d_in[6];
    const float* b1       = (const float*)d_in[7];
    const float* g2       = (const float*)d_in[8];
    const float* b2       = (const float*)d_in[9];
    const float* fc1_w    = (const float*)d_in[10];
    const float* fc1_b    = (const float*)d_in[11];
    const float* fc2_w    = (const float*)d_in[12];
    const float* fc2_b    = (const float*)d_in[13];
    const int*   rel_idx  = (const int*)  d_in[14];
    const float* amask    = (const float*)d_in[15];
    float* out = (float*)d_out;

    float *bufA, *bufB, *biasT;
    __half* wh;
    cudaGetSymbolAddress((void**)&bufA, g_bufA);
    cudaGetSymbolAddress((void**)&bufB, g_bufB);
    cudaGetSymbolAddress((void**)&biasT, g_biasT);
    cudaGetSymbolAddress((void**)&wh, g_wh);

    __half* win  = (__half*)bufA;
    __half* qkvb = (__half*)bufB;                  // fp16 qkv
    __half* att  = (__half*)bufA;                  // win dead
    float*  x1   = bufB;                           // qkv dead after attn
    __half* h2   = (__half*)(bufB + (size_t)MTOK * CC);
    __half* mlpc = (__half*)bufA;                  // att dead

    cudaFuncSetAttribute(gemm_tc<EPI_QKVH>, cudaFuncAttributeMaxDynamicSharedMemorySize, SMEM_DYN);
    cudaFuncSetAttribute(gemm_tc<EPI_PROJ>, cudaFuncAttributeMaxDynamicSharedMemorySize, SMEM_DYN);
    cudaFuncSetAttribute(gemm_tc<EPI_GELU>, cudaFuncAttributeMaxDynamicSharedMemorySize, SMEM_DYN);
    cudaFuncSetAttribute(gemm_tc<EPI_RES>,  cudaFuncAttributeMaxDynamicSharedMemorySize, SMEM_DYN);

    const int LN_BLOCKS = MTOK / 8;

    // 0) prep: fp16 weights + bias pre-gather (all tiny)
    w2h_kernel<<<(C3*CC   + 255)/256, 256>>>(qkv_w,  wh + WOFF_QKV,  C3*CC);
    w2h_kernel<<<(CC*CC   + 255)/256, 256>>>(proj_w, wh + WOFF_PROJ, CC*CC);
    w2h_kernel<<<(MLPH*CC + 255)/256, 256>>>(fc1_w,  wh + WOFF_FC1,  MLPH*CC);
    w2h_kernel<<<(CC*MLPH + 255)/256, 256>>>(fc2_w,  wh + WOFF_FC2,  CC*MLPH);
    bias_gather_kernel<<<(NHEAD*NTOK*NTOK + 255)/256, 256>>>(rpb, rel_idx, biasT);

    // 1) LN1 + shift + window partition (gather) -> fp16
    ln_kernel<true><<<LN_BLOCKS, 256>>>(x, g1, b1, win);

    // 2) QKV GEMM -> fp16 qkv
    gemm_tc<EPI_QKVH><<<dim3(C3 / 64, MTOK / 256), 256, SMEM_DYN>>>(
        win, wh + WOFF_QKV, qkv_b, nullptr, qkvb, MTOK, C3, CC);

    // 3) attention (fp16 MMA) -> fp16 att
    attn_kernel<<<dim3(BB * NWIN, NHEAD), 128>>>(qkvb, biasT, amask, att);

    // 4) proj GEMM + scatter + residual -> x1 f32
    gemm_tc<EPI_PROJ><<<dim3(CC / 64, MTOK / 256), 256, SMEM_DYN>>>(
        att, wh + WOFF_PROJ, proj_b, x, x1, MTOK, CC, CC);

    // 5) LN2 -> fp16
    ln_kernel<false><<<LN_BLOCKS, 256>>>(x1, g2, b2, h2);

    // 6/7) MLP in 4 row-chunks
    for (int c = 0; c < 4; c++) {
        size_t roff = (size_t)c * MCHUNK;
        gemm_tc<EPI_GELU><<<dim3(MLPH / 64, MCHUNK / 256), 256, SMEM_DYN>>>(
            h2 + roff * CC, wh + WOFF_FC1, fc1_b, nullptr, mlpc,
            MCHUNK, MLPH, CC);
        gemm_tc<EPI_RES><<<dim3(CC / 64, MCHUNK / 256), 256, SMEM_DYN>>>(
            mlpc, wh + WOFF_FC2, fc2_b, x1 + roff * CC, out + roff * CC,
            MCHUNK, CC, MLPH);
    }

    (void)in_sizes; (void)n_in; (void)out_size;
}

// round 12
// speedup vs baseline: 3.9078x; 1.0431x over previous
#include <cuda_runtime.h>
#include <cuda_fp16.h>
#include <math.h>
#include <stdint.h>

// ---------------- problem constants ----------------
#define BB     8
#define HH     128
#define WW     384
#define CC     192
#define NHEAD  6
#define WSZ    8
#define SSZ    4
#define HDIM   32
#define NWIN   768
#define NTOK   64
#define HWSZ   (HH*WW)             // 49152
#define MTOK   (BB*HWSZ)           // 393216
#define C3     (3*CC)              // 576
#define MLPH   (4*CC)              // 768
#define SCALE  0.1767766952966369f
#define MCHUNK (MTOK/4)            // 98304

// ---------------- scratch (aliased; keep <2GB total for host link) --------
__device__ float g_bufA[(size_t)MTOK * CC];    // win/att/mlp (as half) reuse
__device__ float g_bufB[(size_t)MTOK * C3];    // qkv(h) -> (x1 | h2)
__device__ float g_biasT[NHEAD * NTOK * NTOK]; // rpb[rel_idx] pre-gathered
__device__ __half g_wh[C3*CC + CC*CC + MLPH*CC + CC*MLPH]; // fp16 weights

#define WOFF_QKV  0
#define WOFF_PROJ (C3*CC)
#define WOFF_FC1  (C3*CC + CC*CC)
#define WOFF_FC2  (C3*CC + CC*CC + MLPH*CC)
#define WTOT      (C3*CC + CC*CC + MLPH*CC + CC*MLPH)   // 442368

__device__ __forceinline__ int win_to_tok(int m) {
    int b  = m / HWSZ;
    int r  = m - b * HWSZ;
    int w  = r >> 6;
    int nt = r & 63;
    int wrow = w / 48;
    int wcol = w - wrow * 48;
    int sh = (wrow << 3) + (nt >> 3);
    int sw = (wcol << 3) + (nt & 7);
    int fh = (sh + SSZ) & (HH - 1);
    int fw = sw + SSZ; if (fw >= WW) fw -= WW;
    return b * HWSZ + fh * WW + fw;
}

// ---------------- merged prep: all weights -> fp16 -----------------------
__global__ void prep_kernel(const float* __restrict__ qkv_w,
                            const float* __restrict__ proj_w,
                            const float* __restrict__ fc1_w,
                            const float* __restrict__ fc2_w,
                            __half* __restrict__ wh) {
    int i = blockIdx.x * blockDim.x + threadIdx.x;
    if (i >= WTOT) return;
    float v;
    if (i < WOFF_PROJ)      v = qkv_w[i];
    else if (i < WOFF_FC1)  v = proj_w[i - WOFF_PROJ];
    else if (i < WOFF_FC2)  v = fc1_w[i - WOFF_FC1];
    else                    v = fc2_w[i - WOFF_FC2];
    wh[i] = __float2half_rn(v);
}
__global__ void bias_gather_kernel(const float* __restrict__ rpb,
                                   const int* __restrict__ rel_idx,
                                   float* __restrict__ biasT) {
    int i = blockIdx.x * blockDim.x + threadIdx.x;
    if (i >= NHEAD * NTOK * NTOK) return;
    int h = i / (NTOK * NTOK), e = i % (NTOK * NTOK);
    biasT[i] = rpb[rel_idx[e] * NHEAD + h];
}

// ---------------- LayerNorm (one warp per token) -> fp16 out --------------
template<bool GATHER>
__global__ void ln_kernel(const float* __restrict__ x,
                          const float* __restrict__ gamma,
                          const float* __restrict__ beta,
                          __half* __restrict__ out) {
    int warp = blockIdx.x * (blockDim.x >> 5) + (threadIdx.x >> 5);
    if (warp >= MTOK) return;
    int lane = threadIdx.x & 31;
    int src = GATHER ? win_to_tok(warp) : warp;
    const float* xr = x + (size_t)src * CC;
    float v[6], s = 0.f, ss = 0.f;
#pragma unroll
    for (int i = 0; i < 6; i++) {
        float t = xr[lane + i * 32];
        v[i] = t; s += t; ss += t * t;
    }
#pragma unroll
    for (int o = 16; o; o >>= 1) {
        s  += __shfl_xor_sync(0xffffffffu, s,  o);
        ss += __shfl_xor_sync(0xffffffffu, ss, o);
    }
    float mean = s * (1.f / CC);
    float var  = ss * (1.f / CC) - mean * mean;
    float rstd = rsqrtf(var + 1e-5f);
    __half* orow = out + (size_t)warp * CC;
#pragma unroll
    for (int i = 0; i < 6; i++) {
        int c = lane + i * 32;
        orow[c] = __float2half_rn((v[i] - mean) * rstd * gamma[c] + beta[c]);
    }
}

// ---------------- shared MMA helpers --------------------------------------
__device__ __forceinline__ void cp16(uint32_t s, const void* g) {
    asm volatile("cp.async.cg.shared.global [%0], [%1], 16;" :: "r"(s), "l"(g));
}
__device__ __forceinline__ void ldsm4(uint32_t* r, uint32_t addr) {
    asm volatile("ldmatrix.sync.aligned.m8n8.x4.shared.b16 {%0,%1,%2,%3}, [%4];"
        : "=r"(r[0]), "=r"(r[1]), "=r"(r[2]), "=r"(r[3]) : "r"(addr));
}
__device__ __forceinline__ void mma_f16(float c[4],
        uint32_t a0, uint32_t a1, uint32_t a2, uint32_t a3,
        uint32_t b0, uint32_t b1) {
    asm volatile(
        "mma.sync.aligned.m16n8k16.row.col.f32.f16.f16.f32 "
        "{%0,%1,%2,%3},{%4,%5,%6,%7},{%8,%9},{%0,%1,%2,%3};"
        : "+f"(c[0]), "+f"(c[1]), "+f"(c[2]), "+f"(c[3])
        : "r"(a0), "r"(a1), "r"(a2), "r"(a3), "r"(b0), "r"(b1));
}

// ---------------- FP16 mma GEMM, BM=128 BN=64 BK=32, 4-stage --------------
// out[m,n] = sum_k A[m,k]*W[n,k] (+epilogue). 256 threads = 8 warps (4Mx2N),
// warp tile 32x32 = 2x4 m16n8k16 MMAs x 2 k-steps. Stage = 15.36KB; 4 stages
// = 61.4KB/CTA -> 3 CTAs/SM (24 warps) with prefetch depth 3. One
// __syncthreads per iter; fill for slot (it-1)%4 issued after the sync that
// proves all warps consumed it (same ordering proof as the 3-stage ring).
#define EPI_QKVH 0   // out = half(acc + bias)
#define EPI_PROJ 1   // f32: scatter + residual
#define EPI_GELU 2   // half: gelu(acc + bias)
#define EPI_RES  3   // f32: residual

#define NSTAGE   4
#define AH_STAGE (128*40)
#define BH_STAGE (64*40)
#define SMEM_DYN (NSTAGE * (AH_STAGE + BH_STAGE) * 2)

template<int EPI>
__global__ __launch_bounds__(256, 3)
void gemm_tc(const __half* __restrict__ A, const __half* __restrict__ W,
             const float* __restrict__ bias, const float* __restrict__ res,
             void* __restrict__ outv, int M, int N, int K) {
    extern __shared__ __half smem_h[];
    __half* As = smem_h;
    __half* Bs = smem_h + NSTAGE * AH_STAGE;

    int tid  = threadIdx.x;
    int lane = tid & 31, warp = tid >> 5;
    int grp  = lane >> 2, tig = lane & 3;
    int sub  = lane >> 3, tr8 = lane & 7;
    int m0 = blockIdx.y * 128, n0 = blockIdx.x * 64;
    int wm = (warp & 3) * 32;                 // 4 warps over M
    int wn = (warp >> 2) * 32;                // 2 warps over N
    int ldRow = tid >> 2;                     // 0..63
    int ldColh = (tid & 3) << 3;              // 0,8,16,24 (halves)

    uint32_t sA = (uint32_t)__cvta_generic_to_shared(As);
    uint32_t sB = (uint32_t)__cvta_generic_to_shared(Bs);

    int rowAh[2], rowBh[2];
#pragma unroll
    for (int i = 0; i < 2; i++)
        rowAh[i] = (wm + i * 16 + (sub & 1) * 8 + tr8) * 40 + (sub >> 1) * 8;
#pragma unroll
    for (int g = 0; g < 2; g++)
        rowBh[g] = (wn + g * 16 + (sub & 1) * 8 + tr8) * 40 + (sub >> 1) * 8;

    float acc[2][4][4] = {};
    const int niter = K >> 5;

#define ISSUE(it) do {                                                        \
        int s_ = (it) % NSTAGE; int k0_ = (it) << 5;                          \
        _Pragma("unroll")                                                     \
        for (int r = 0; r < 128; r += 64)                                     \
            cp16(sA + 2u*(s_*AH_STAGE + (ldRow + r)*40 + ldColh),             \
                 A + (size_t)(m0 + ldRow + r) * K + k0_ + ldColh);            \
        cp16(sB + 2u*(s_*BH_STAGE + ldRow*40 + ldColh),                       \
             W + (size_t)(n0 + ldRow) * K + k0_ + ldColh);                    \
    } while (0)

    // prologue: prefetch 3 stages
#pragma unroll
    for (int p = 0; p < NSTAGE - 1; p++) {
        if (p < niter) { ISSUE(p); }
        asm volatile("cp.async.commit_group;");
    }

    for (int it = 0; it < niter; it++) {
        asm volatile("cp.async.wait_group %0;" :: "n"(NSTAGE - 2));
        __syncthreads();
        if (it + NSTAGE - 1 < niter) { ISSUE(it + NSTAGE - 1); }
        asm volatile("cp.async.commit_group;");

        uint32_t baseA = sA + 2u * ((it % NSTAGE) * AH_STAGE);
        uint32_t baseB = sB + 2u * ((it % NSTAGE) * BH_STAGE);
#pragma unroll
        for (int ks = 0; ks < 2; ks++) {
            int kb = ks * 16;
            uint32_t a[2][4], b[2][4];
#pragma unroll
            for (int i = 0; i < 2; i++)
                ldsm4(a[i], baseA + 2u * (rowAh[i] + kb));
            ldsm4(b[0], baseB + 2u * (rowBh[0] + kb));
            ldsm4(b[1], baseB + 2u * (rowBh[1] + kb));
#pragma unroll
            for (int i = 0; i < 2; i++)
#pragma unroll
                for (int j = 0; j < 4; j++) {
                    int g = j >> 1, jn = j & 1;
                    mma_f16(acc[i][j], a[i][0], a[i][1], a[i][2], a[i][3],
                            b[g][jn], b[g][2 + jn]);
                }
        }
    }
#undef ISSUE

#pragma unroll
    for (int i = 0; i < 2; i++) {
#pragma unroll
        for (int h = 0; h < 2; h++) {
            int m = m0 + wm + i * 16 + grp + h * 8;
            int dst = (EPI == EPI_PROJ) ? win_to_tok(m) : m;
#pragma unroll
            for (int j = 0; j < 4; j++) {
                int n = n0 + wn + j * 8 + 2 * tig;
                float v0 = acc[i][j][h * 2 + 0] + bias[n];
                float v1 = acc[i][j][h * 2 + 1] + bias[n + 1];
                size_t oi = (size_t)dst * N + n;
                if (EPI == EPI_QKVH) {
                    *(__half2*)((__half*)outv + oi) = __floats2half2_rn(v0, v1);
                } else if (EPI == EPI_GELU) {
                    v0 = 0.5f * v0 * (1.f + erff(v0 * 0.70710678118654752f));
                    v1 = 0.5f * v1 * (1.f + erff(v1 * 0.70710678118654752f));
                    *(__half2*)((__half*)outv + oi) = __floats2half2_rn(v0, v1);
                } else {
                    float2 rv = *(const float2*)(res + oi);
                    float2 o = { v0 + rv.x, v1 + rv.y };
                    *(float2*)((float*)outv + oi) = o;
                }
            }
        }
    }
}

// ---------------- windowed attention (fp16 MMA) ---------------------------
// one block per (window, head), 128 threads = 4 warps; warp w owns rows
// 16w..16w+15. QK^T and P.V via m16n8k16; softmax fp32 in smem.
__global__ __launch_bounds__(128)
void attn_kernel(const __half* __restrict__ qkv,
                 const float* __restrict__ biasT,    // [NHEAD][64*64]
                 const float* __restrict__ mask,     // [768][64*64]
                 __half* __restrict__ out) {         // [M,192] half
    __shared__ __half qs[NTOK][40];      // stride 40h: ldsm conflict-free
    __shared__ __half ks_[NTOK][40];
    __shared__ __half vt[HDIM][72];      // V^T; stride 72h conflict-free
    __shared__ float  S[NTOK][NTOK];
    __shared__ __half Ph[NTOK][72];

    int wg = blockIdx.x, head = blockIdx.y, tid = threadIdx.x;
    int lane = tid & 31, warp = tid >> 5;
    int grp = lane >> 2, tig = lane & 3;
    int sub = lane >> 3, tr8 = lane & 7;

    const __half* base = qkv + (size_t)wg * NTOK * C3 + head * HDIM;
    for (int t = tid; t < 256; t += 128) {
        int n = t >> 2, c = t & 3;
        const __half* row = base + (size_t)n * C3 + c * 8;
        *(uint4*)&qs[n][c * 8]  = *(const uint4*)(row);
        *(uint4*)&ks_[n][c * 8] = *(const uint4*)(row + CC);
        uint4 vv = *(const uint4*)(row + 2 * CC);
        __half tmp[8]; *(uint4*)tmp = vv;
#pragma unroll
        for (int i = 0; i < 8; i++) vt[c * 8 + i][n] = tmp[i];
    }
    __syncthreads();

    uint32_t sq = (uint32_t)__cvta_generic_to_shared(qs);
    uint32_t sk = (uint32_t)__cvta_generic_to_shared(ks_);
    uint32_t sv = (uint32_t)__cvta_generic_to_shared(vt);
    uint32_t sp = (uint32_t)__cvta_generic_to_shared(Ph);

    int n0 = warp * 16;
    int rowA8 = n0 + (sub & 1) * 8 + tr8;
    int kA = (sub >> 1) * 8;

    // ---- QK^T -> S (+scale +bias +mask)
    float sc[8][4] = {};
#pragma unroll
    for (int ks = 0; ks < 2; ks++) {
        uint32_t a[4];
        ldsm4(a, sq + 2u * (rowA8 * 40 + kA + ks * 16));
#pragma unroll
        for (int g = 0; g < 4; g++) {
            uint32_t b[4];
            int rowB = g * 16 + (sub & 1) * 8 + tr8;
            ldsm4(b, sk + 2u * (rowB * 40 + kA + ks * 16));
#pragma unroll
            for (int jn = 0; jn < 2; jn++)
                mma_f16(sc[g * 2 + jn], a[0], a[1], a[2], a[3], b[jn], b[2 + jn]);
        }
    }
    const float* bT   = biasT + head * (NTOK * NTOK);
    const float* mrow = mask + (size_t)(wg % NWIN) * (NTOK * NTOK);
#pragma unroll
    for (int j = 0; j < 8; j++) {
#pragma unroll
        for (int h = 0; h < 2; h++) {
            int n = n0 + grp + h * 8;
            int m = j * 8 + 2 * tig;
            int e = n * 64 + m;
            float2 bb = *(const float2*)(bT + e);
            float2 mk = *(const float2*)(mrow + e);
            S[n][m]     = sc[j][h * 2 + 0] * SCALE + bb.x + mk.x;
            S[n][m + 1] = sc[j][h * 2 + 1] * SCALE + bb.y + mk.y;
        }
    }
    __syncthreads();

    for (int r = 0; r < 16; r++) {
        int row = warp * 16 + r;
        float v0 = S[row][lane], v1 = S[row][lane + 32];
        float mx = fmaxf(v0, v1);
#pragma unroll
        for (int o = 16; o; o >>= 1) mx = fmaxf(mx, __shfl_xor_sync(~0u, mx, o));
        float e0 = expf(v0 - mx), e1 = expf(v1 - mx);
        float s = e0 + e1;
#pragma unroll
        for (int o = 16; o; o >>= 1) s += __shfl_xor_sync(~0u, s, o);
        float inv = 1.f / s;
        S[row][lane] = e0 * inv;
        S[row][lane + 32] = e1 * inv;
    }
    __syncthreads();

    for (int t = tid; t < 2048; t += 128) {
        int n = t >> 5, mp = (t & 31) * 2;
        float2 s2 = *(const float2*)&S[n][mp];
        *(__half2*)&Ph[n][mp] = __floats2half2_rn(s2.x, s2.y);
    }
    __syncthreads();

    float oc[4][4] = {};
#pragma unroll
    for (int ks = 0; ks < 4; ks++) {
        uint32_t a[4];
        ldsm4(a, sp + 2u * (rowA8 * 72 + kA + ks * 16));
#pragma unroll
        for (int g = 0; g < 2; g++) {
            uint32_t b[4];
            int rowB = g * 16 + (sub & 1) * 8 + tr8;
            ldsm4(b, sv + 2u * (rowB * 72 + kA + ks * 16));
#pragma unroll
            for (int jn = 0; jn < 2; jn++)
                mma_f16(oc[g * 2 + jn], a[0], a[1], a[2], a[3], b[jn], b[2 + jn]);
        }
    }
    __half* ob = out + (size_t)wg * NTOK * CC + head * HDIM;
#pragma unroll
    for (int j = 0; j < 4; j++) {
#pragma unroll
        for (int h = 0; h < 2; h++) {
            int n = n0 + grp + h * 8;
            int d = j * 8 + 2 * tig;
            *(__half2*)(ob + (size_t)n * CC + d) =
                __floats2half2_rn(oc[j][h * 2], oc[j][h * 2 + 1]);
        }
    }
}

// ---------------- launch ---------------------------------------------------
extern "C" void kernel_launch(void* const* d_in, const int* in_sizes, int n_in,
                              void* d_out, int out_size) {
    const float* x        = (const float*)d_in[0];
    const float* qkv_w    = (const float*)d_in[1];
    const float* qkv_b    = (const float*)d_in[2];
    const float* rpb      = (const float*)d_in[3];
    const float* proj_w   = (const float*)d_in[4];
    const float* proj_b   = (const float*)d_in[5];
    const float* g1       = (const float*)d_in[6];
    const float* b1       = (const float*)d_in[7];
    const float* g2       = (const float*)d_in[8];
    const float* b2       = (const float*)d_in[9];
    const float* fc1_w    = (const float*)d_in[10];
    const float* fc1_b    = (const float*)d_in[11];
    const float* fc2_w    = (const float*)d_in[12];
    const float* fc2_b    = (const float*)d_in[13];
    const int*   rel_idx  = (const int*)  d_in[14];
    const float* amask    = (const float*)d_in[15];
    float* out = (float*)d_out;

    float *bufA, *bufB, *biasT;
    __half* wh;
    cudaGetSymbolAddress((void**)&bufA, g_bufA);
    cudaGetSymbolAddress((void**)&bufB, g_bufB);
    cudaGetSymbolAddress((void**)&biasT, g_biasT);
    cudaGetSymbolAddress((void**)&wh, g_wh);

    __half* win  = (__half*)bufA;
    __half* qkvb = (__half*)bufB;                  // fp16 qkv
    __half* att  = (__half*)bufA;                  // win dead
    float*  x1   = bufB;                           // qkv dead after attn
    __half* h2   = (__half*)(bufB + (size_t)MTOK * CC);
    __half* mlpc = (__half*)bufA;                  // att dead

    cudaFuncSetAttribute(gemm_tc<EPI_QKVH>, cudaFuncAttributeMaxDynamicSharedMemorySize, SMEM_DYN);
    cudaFuncSetAttribute(gemm_tc<EPI_PROJ>, cudaFuncAttributeMaxDynamicSharedMemorySize, SMEM_DYN);
    cudaFuncSetAttribute(gemm_tc<EPI_GELU>, cudaFuncAttributeMaxDynamicSharedMemorySize, SMEM_DYN);
    cudaFuncSetAttribute(gemm_tc<EPI_RES>,  cudaFuncAttributeMaxDynamicSharedMemorySize, SMEM_DYN);

    const int LN_BLOCKS = MTOK / 8;

    // 0) prep: fp16 weights (1 kernel) + bias pre-gather
    prep_kernel<<<(WTOT + 255) / 256, 256>>>(qkv_w, proj_w, fc1_w, fc2_w, wh);
    bias_gather_kernel<<<(NHEAD*NTOK*NTOK + 255)/256, 256>>>(rpb, rel_idx, biasT);

    // 1) LN1 + shift + window partition (gather) -> fp16
    ln_kernel<true><<<LN_BLOCKS, 256>>>(x, g1, b1, win);

    // 2) QKV GEMM -> fp16 qkv
    gemm_tc<EPI_QKVH><<<dim3(C3 / 64, MTOK / 128), 256, SMEM_DYN>>>(
        win, wh + WOFF_QKV, qkv_b, nullptr, qkvb, MTOK, C3, CC);

    // 3) attention (fp16 MMA) -> fp16 att
    attn_kernel<<<dim3(BB * NWIN, NHEAD), 128>>>(qkvb, biasT, amask, att);

    // 4) proj GEMM + scatter + residual -> x1 f32
    gemm_tc<EPI_PROJ><<<dim3(CC / 64, MTOK / 128), 256, SMEM_DYN>>>(
        att, wh + WOFF_PROJ, proj_b, x, x1, MTOK, CC, CC);

    // 5) LN2 -> fp16
    ln_kernel<false><<<LN_BLOCKS, 256>>>(x1, g2, b2, h2);

    // 6/7) MLP in 4 row-chunks
    for (int c = 0; c < 4; c++) {
        size_t roff = (size_t)c * MCHUNK;
        gemm_tc<EPI_GELU><<<dim3(MLPH / 64, MCHUNK / 128), 256, SMEM_DYN>>>(
            h2 + roff * CC, wh + WOFF_FC1, fc1_b, nullptr, mlpc,
            MCHUNK, MLPH, CC);
        gemm_tc<EPI_RES><<<dim3(CC / 64, MCHUNK / 128), 256, SMEM_DYN>>>(
            mlpc, wh + WOFF_FC2, fc2_b, x1 + roff * CC, out + roff * CC,
            MCHUNK, CC, MLPH);
    }

    (void)in_sizes; (void)n_in; (void)out_size;
}